// round 8
// baseline (speedup 1.0000x reference)
#include <cuda_runtime.h>
#include <math.h>

#define GRID 128
#define TPB  256
#define Bp   512
#define Dd   64
#define Cc   512
#define NBs  8
#define MC   8
#define NBINS 32768
#define BIN_SC ((float)NBINS/64.0f)

__device__ float g_hA[Bp*Cc];
__device__ float g_hB[Bp*Cc];
__device__ float g_d2[Bp*Bp];
__device__ float g_temb[NBs*2*Cc];
__device__ float g_tg1[NBs*Cc];
__device__ float g_bias1[NBs*Cc];
__device__ float g_betas[NBs+1];
__device__ int   g_hist[2][NBINS];
__device__ unsigned long long g_bar = 0ULL;          // global barrier counter
__device__ unsigned long long g_gbar[8*16];          // group barriers (padded 128B)
__device__ unsigned long long g_hdone = 0ULL;        // pairwise-done flag counter
// weights pre-converted to tf32 bit patterns (stored as float bits)
__device__ float g_Win[Dd*Cc];
__device__ float g_Wh[3*Cc*Cc];

#define ASTR 36   // A smem row stride (floats): conflict-free frag loads
#define WSTR 40   // W smem row stride

struct SmG { float A[2][2][64*ASTR]; float W[2][2][32*WSTR]; float red[64*33]; };
struct SmP { float Xi[32*64]; float Xj[64*64]; };
struct SmU { float w[4][Bp]; float compm[4][MC]; float wm[4][MC]; };
struct SmM { int cnt[TPB]; float v[2]; };
union Smem { SmG g; SmP p; SmU u; SmM m; };

__device__ __forceinline__ float gelu_t(float x){
    float x3 = x*x*x;
    return 0.5f*x*(1.0f+tanhf(0.7978845608028654f*(x+0.044715f*x3)));
}

__device__ __forceinline__ unsigned f2tf(float x){
    unsigned u;
    asm("cvt.rna.tf32.f32 %0, %1;" : "=r"(u) : "f"(x));
    return u;
}
__device__ __forceinline__ float f2tf_f(float x){ return __uint_as_float(f2tf(x)); }

__device__ __forceinline__ void mma_tf32(float* acc,
    unsigned a0, unsigned a1, unsigned a2, unsigned a3,
    unsigned b0, unsigned b1)
{
    asm volatile(
        "mma.sync.aligned.m16n8k8.row.col.f32.tf32.tf32.f32 "
        "{%0,%1,%2,%3}, {%4,%5,%6,%7}, {%8,%9}, {%0,%1,%2,%3};"
        : "+f"(acc[0]), "+f"(acc[1]), "+f"(acc[2]), "+f"(acc[3])
        : "r"(a0), "r"(a1), "r"(a2), "r"(a3), "r"(b0), "r"(b1));
}

// global grid barrier (monotone counter; safe across graph replays)
__device__ __forceinline__ void gridbar(){
    __threadfence();
    __syncthreads();
    if (threadIdx.x == 0){
        unsigned long long old = atomicAdd(&g_bar, 1ULL);
        unsigned long long target = (old/GRID + 1ULL)*GRID;
        while (*(volatile unsigned long long*)&g_bar < target) { }
    }
    __syncthreads();
    __threadfence();
}

// 16-block group barrier (per m-slab); cheap, no cross-group skew coupling
__device__ __forceinline__ void groupbar(int grp){
    __threadfence();
    __syncthreads();
    if (threadIdx.x == 0){
        unsigned long long* ctr = &g_gbar[grp*16];
        unsigned long long old = atomicAdd(ctr, 1ULL);
        unsigned long long target = (old/16ULL + 1ULL)*16ULL;
        while (*(volatile unsigned long long*)ctr < target) { }
    }
    __syncthreads();
    __threadfence();
}

// one 64x32 output tile of C = act(A@W + bias) via tf32 tensor cores.
// 256 threads, 2-way K-split (group = tid>>7); W holds tf32 bit patterns.
// convA: round A to tf32 while staging (for fp32 inputs).
// Output activations stored tf32-rounded (consumed by next MMA layer).
__device__ __forceinline__ void gemm_tile_tc(
    const float* __restrict__ A, int Astr, const float* __restrict__ W, int Wstr,
    int m0, int n0, int klen,
    const float* __restrict__ bias, int act, int convA, int convOut,
    float* __restrict__ C, int Cstr, Smem* sm)
{
    int tid  = threadIdx.x;
    int gid  = tid >> 7;            // K-split group (0/1)
    int tg   = tid & 127;
    int warp = tg >> 5, lane = tid & 31;
    int g = lane >> 2, t = lane & 3;

    int arow = tg >> 1;             // 0..63
    int kseg = (tg & 1) * 16;       // 0 or 16
    int wk   = tg >> 2;             // 0..31
    int nseg = (tg & 3) * 8;        // 0,8,16,24

    int khalf = klen >> 1;
    int kb0   = gid*khalf;
    int NC    = khalf >> 5;

    float acc[4][4] = {};
    float4 ra[4], rw[2];

    #pragma unroll
    for (int q = 0; q < 4; q++)
        ra[q] = *(const float4*)&A[(size_t)(m0+arow)*Astr + kb0 + kseg + 4*q];
    #pragma unroll
    for (int q = 0; q < 2; q++)
        rw[q] = *(const float4*)&W[(size_t)(kb0+wk)*Wstr + n0 + nseg + 4*q];
    if (convA){
        #pragma unroll
        for (int q = 0; q < 4; q++){
            ra[q].x = f2tf_f(ra[q].x); ra[q].y = f2tf_f(ra[q].y);
            ra[q].z = f2tf_f(ra[q].z); ra[q].w = f2tf_f(ra[q].w);
        }
    }
    {
        float* As = sm->g.A[gid][0]; float* Ws = sm->g.W[gid][0];
        #pragma unroll
        for (int q = 0; q < 4; q++) *(float4*)&As[arow*ASTR + kseg + 4*q] = ra[q];
        #pragma unroll
        for (int q = 0; q < 2; q++) *(float4*)&Ws[wk*WSTR + nseg + 4*q] = rw[q];
    }

    for (int c = 0; c < NC; c++){
        __syncthreads();
        int cb = c & 1;
        if (c+1 < NC){
            int kb = kb0 + (c+1)*32;
            #pragma unroll
            for (int q = 0; q < 4; q++)
                ra[q] = *(const float4*)&A[(size_t)(m0+arow)*Astr + kb + kseg + 4*q];
            #pragma unroll
            for (int q = 0; q < 2; q++)
                rw[q] = *(const float4*)&W[(size_t)(kb+wk)*Wstr + n0 + nseg + 4*q];
            if (convA){
                #pragma unroll
                for (int q = 0; q < 4; q++){
                    ra[q].x = f2tf_f(ra[q].x); ra[q].y = f2tf_f(ra[q].y);
                    ra[q].z = f2tf_f(ra[q].z); ra[q].w = f2tf_f(ra[q].w);
                }
            }
        }
        const float* As = sm->g.A[gid][cb];
        const float* Ws = sm->g.W[gid][cb];
        #pragma unroll
        for (int kk = 0; kk < 4; kk++){
            int ab = (16*warp + g)*ASTR + kk*8;
            unsigned a0 = __float_as_uint(As[ab + t]);
            unsigned a1 = __float_as_uint(As[ab + 8*ASTR + t]);
            unsigned a2 = __float_as_uint(As[ab + t + 4]);
            unsigned a3 = __float_as_uint(As[ab + 8*ASTR + t + 4]);
            #pragma unroll
            for (int c4 = 0; c4 < 4; c4++){
                unsigned b0 = __float_as_uint(Ws[(kk*8 + t)*WSTR + c4*8 + g]);
                unsigned b1 = __float_as_uint(Ws[(kk*8 + t + 4)*WSTR + c4*8 + g]);
                mma_tf32(acc[c4], a0, a1, a2, a3, b0, b1);
            }
        }
        if (c+1 < NC){
            int nb = cb ^ 1;
            float* As2 = sm->g.A[gid][nb]; float* Ws2 = sm->g.W[gid][nb];
            #pragma unroll
            for (int q = 0; q < 4; q++) *(float4*)&As2[arow*ASTR + kseg + 4*q] = ra[q];
            #pragma unroll
            for (int q = 0; q < 2; q++) *(float4*)&Ws2[wk*WSTR + nseg + 4*q] = rw[q];
        }
    }

    __syncthreads();
    int r0 = 16*warp + g;
    if (gid == 1){
        #pragma unroll
        for (int c4 = 0; c4 < 4; c4++){
            int col = c4*8 + 2*t;
            sm->g.red[r0*33 + col]       = acc[c4][0];
            sm->g.red[r0*33 + col + 1]   = acc[c4][1];
            sm->g.red[(r0+8)*33 + col]   = acc[c4][2];
            sm->g.red[(r0+8)*33 + col+1] = acc[c4][3];
        }
    }
    __syncthreads();
    if (gid == 0){
        #pragma unroll
        for (int c4 = 0; c4 < 4; c4++){
            int col = c4*8 + 2*t;
            float v00 = acc[c4][0] + sm->g.red[r0*33 + col];
            float v01 = acc[c4][1] + sm->g.red[r0*33 + col + 1];
            float v10 = acc[c4][2] + sm->g.red[(r0+8)*33 + col];
            float v11 = acc[c4][3] + sm->g.red[(r0+8)*33 + col+1];
            int n = n0 + col;
            if (bias){ v00 += bias[n]; v01 += bias[n+1]; v10 += bias[n]; v11 += bias[n+1]; }
            if (act){ v00 = gelu_t(v00); v01 = gelu_t(v01); v10 = gelu_t(v10); v11 = gelu_t(v11); }
            if (convOut){ v00 = f2tf_f(v00); v01 = f2tf_f(v01); v10 = f2tf_f(v10); v11 = f2tf_f(v11); }
            C[(size_t)(m0+r0)*Cstr + n]       = v00;
            C[(size_t)(m0+r0)*Cstr + n + 1]   = v01;
            C[(size_t)(m0+r0+8)*Cstr + n]     = v10;
            C[(size_t)(m0+r0+8)*Cstr + n + 1] = v11;
        }
    }
    __syncthreads();
}

// 32x64 tile of pairwise squared distances + histogram (256 threads)
__device__ __forceinline__ void pairwise_tile(const float* __restrict__ x, int i0, int j0,
                                              int* __restrict__ hist, Smem* sm){
    int tid = threadIdx.x;
    #pragma unroll
    for (int q = 0; q < 2; q++){
        int idx = tid + 256*q;
        int r = idx>>4, c4 = (idx&15)*4;
        if (r < 32){
            float4 v = *(const float4*)&x[(i0+r)*Dd + c4];
            sm->p.Xi[(c4+0)*32+r]=v.x; sm->p.Xi[(c4+1)*32+r]=v.y;
            sm->p.Xi[(c4+2)*32+r]=v.z; sm->p.Xi[(c4+3)*32+r]=v.w;
        }
    }
    #pragma unroll
    for (int q = 0; q < 4; q++){
        int idx = tid + 256*q;
        int row = idx>>4, c4 = (idx&15)*4;
        float4 v = *(const float4*)&x[(j0+row)*Dd + c4];
        sm->p.Xj[(c4+0)*64+row]=v.x; sm->p.Xj[(c4+1)*64+row]=v.y;
        sm->p.Xj[(c4+2)*64+row]=v.z; sm->p.Xj[(c4+3)*64+row]=v.w;
    }
    __syncthreads();
    int ty = tid>>4, tx = tid&15;          // 16x16 thread grid, 2x4 micro
    float acc[2][4] = {};
    #pragma unroll
    for (int k = 0; k < 64; k++){
        float a0 = sm->p.Xi[k*32 + ty*2];
        float a1 = sm->p.Xi[k*32 + ty*2 + 1];
        float4 b = *(const float4*)&sm->p.Xj[k*64 + tx*4];
        float d;
        d=a0-b.x; acc[0][0]+=d*d;  d=a0-b.y; acc[0][1]+=d*d;
        d=a0-b.z; acc[0][2]+=d*d;  d=a0-b.w; acc[0][3]+=d*d;
        d=a1-b.x; acc[1][0]+=d*d;  d=a1-b.y; acc[1][1]+=d*d;
        d=a1-b.z; acc[1][2]+=d*d;  d=a1-b.w; acc[1][3]+=d*d;
    }
    #pragma unroll
    for (int i = 0; i < 2; i++){
        int gi = i0 + ty*2 + i;
        #pragma unroll
        for (int j = 0; j < 4; j++){
            int gj = j0 + tx*4 + j;
            float d2 = acc[i][j];
            g_d2[gi*Bp + gj] = d2;
            float dist = sqrtf(d2 > 0.f ? d2 : 1e-12f);
            int bin = (int)(dist*BIN_SC);
            if (bin > NBINS-1) bin = NBINS-1;
            atomicAdd(&hist[bin], 1);
        }
    }
    __syncthreads();
}

// every block computes the exact median locally (prefix scan over chunk counts)
__device__ __forceinline__ float median_local(const int* __restrict__ hist, Smem* sm){
    int tid = threadIdx.x;
    const int per = NBINS/TPB;   // 128
    int ssum = 0;
    #pragma unroll 8
    for (int b = 0; b < per; b++) ssum += hist[tid*per + b];
    sm->m.cnt[tid] = ssum;
    __syncthreads();
    #pragma unroll
    for (int off = 1; off < TPB; off <<= 1){
        int v = (tid >= off) ? sm->m.cnt[tid-off] : 0;
        __syncthreads();
        sm->m.cnt[tid] += v;
        __syncthreads();
    }
    long long k1 = (long long)Bp*Bp/2, k2 = k1 + 1;
    int prev = tid ? sm->m.cnt[tid-1] : 0;
    int cur  = sm->m.cnt[tid];
    if (prev < k1 && k1 <= cur){
        int cum = prev, b = tid*per;
        while (cum + hist[b] < k1){ cum += hist[b]; b++; }
        sm->m.v[0] = ((float)b + 0.5f)/BIN_SC;
    }
    if (prev < k2 && k2 <= cur){
        int cum = prev, b = tid*per;
        while (cum + hist[b] < k2){ cum += hist[b]; b++; }
        sm->m.v[1] = ((float)b + 0.5f)/BIN_SC;
    }
    __syncthreads();
    float med = 0.5f*(sm->m.v[0] + sm->m.v[1]);
    float ht = med*med / logf((float)Bp);
    __syncthreads();     // everyone has read v[] before the union is reused
    return ht;
}

__global__ void __launch_bounds__(TPB, 1)
cmcd_fused(const float* __restrict__ particles, const float* __restrict__ noises,
           const float* __restrict__ grid_t, const float* __restrict__ eps,
           const float* __restrict__ means, const float* __restrict__ phase,
           const float* __restrict__ in_W, const float* __restrict__ in_b,
           const float* __restrict__ t_W1, const float* __restrict__ t_b1,
           const float* __restrict__ t_W2, const float* __restrict__ t_b2,
           const float* __restrict__ h_W, const float* __restrict__ h_b,
           const float* __restrict__ out_W, const float* __restrict__ out_b,
           float* __restrict__ out)
{
    extern __shared__ unsigned char smem_raw[];
    Smem* sm = reinterpret_cast<Smem*>(smem_raw);
    __shared__ unsigned long long sm_hold;   // my arrival ticket on g_hdone
    int blk = blockIdx.x, tid = threadIdx.x;
    int gtid = blk*TPB + tid;
    const int NT = GRID*TPB;
    int grp = blk >> 4;                      // m-slab group (16 blocks)

    // ── S0: copy slice 0, zero hists, temb, betas, tf32-convert weights ──
    for (int idx = gtid; idx < Bp*Dd; idx += NT) out[idx] = particles[idx];
    for (int idx = gtid; idx < 2*NBINS; idx += NT) g_hist[0][idx] = 0;
    for (int idx = gtid; idx < Dd*Cc; idx += NT) g_Win[idx] = f2tf_f(in_W[idx]);
    for (int idx = gtid; idx < 3*Cc*Cc; idx += NT) g_Wh[idx] = f2tf_f(h_W[idx]);
    for (int idx = gtid; idx < NBs*2*Cc; idx += NT){
        int s = idx >> 10, c = idx & 1023;
        float t = (float)s;
        int cc = (c < Cc) ? c : c - Cc;
        float coeff = 0.1f + (float)cc*(99.9f/511.0f);
        float e = coeff*t + phase[cc];
        g_temb[idx] = (c < Cc) ? sinf(e) : cosf(e);
    }
    if (gtid == 0){
        float cum = 0.f;
        g_betas[0] = 0.f;
        for (int j = 0; j < NBs; j++){
            float sg = 1.f/(1.f+expf(-grid_t[j]));
            cum += sg;
            g_betas[j+1] = cum;
        }
        float inv = 1.f/cum;
        for (int j = 1; j <= NBs; j++) g_betas[j] *= inv;
    }
    gridbar();

    // ── S1: t-MLP layer 1 (8-way K-split + shuffle reduce) ──
    {
        int oidx = gtid >> 3;       // 0..4095
        int sl   = gtid & 7;
        int s = oidx >> 9, c = oidx & 511;
        float acc = 0.f;
        const float* tb = g_temb + s*2*Cc;
        int kb = sl*128;
        #pragma unroll 4
        for (int k = kb; k < kb+128; k++) acc += tb[k]*t_W1[k*Cc + c];
        #pragma unroll
        for (int o = 1; o < 8; o <<= 1) acc += __shfl_xor_sync(0xffffffffu, acc, o);
        if (sl == 0) g_tg1[oidx] = gelu_t(acc + t_b1[c]);
    }
    gridbar();

    // ── S2: t-MLP layer 2 + in_b → fused input bias ──
    {
        int oidx = gtid >> 3;
        int sl   = gtid & 7;
        int s = oidx >> 9, c = oidx & 511;
        float acc = 0.f;
        const float* gb = g_tg1 + s*Cc;
        int kb = sl*64;
        #pragma unroll 4
        for (int k = kb; k < kb+64; k++) acc += gb[k]*t_W2[k*Cc + c];
        #pragma unroll
        for (int o = 1; o < 8; o <<= 1) acc += __shfl_xor_sync(0xffffffffu, acc, o);
        if (sl == 0) g_bias1[oidx] = acc + t_b2[c] + in_b[c];
    }
    gridbar();

    int m0 = grp * 64;            // 8 m-tiles of 64 rows
    int n0 = (blk & 15) * 32;     // 16 n-tiles of 32 cols

    for (int s = 0; s < NBs; s++){
        const float* x = out + (size_t)s*Bp*Dd;
        float* xn      = out + (size_t)(s+1)*Bp*Dd;
        int par = s & 1;

        // ── P1: input layer (K=64, conv A) + pairwise d2/hist, then ARRIVE ──
        gemm_tile_tc(x, Dd, g_Win, Cc, m0, n0, Dd, g_bias1 + s*Cc, 1, 1, 1, g_hA, Cc, sm);
        pairwise_tile(x, (blk>>3)*32, (blk&7)*64, g_hist[par], sm);
        __threadfence();
        __syncthreads();
        if (tid == 0) sm_hold = atomicAdd(&g_hdone, 1ULL);
        groupbar(grp);

        // ── P2-P4: hidden layers (group-local sync only) ──
        gemm_tile_tc(g_hA, Cc, g_Wh + 0*Cc*Cc, Cc, m0, n0, Cc, h_b + 0*Cc, 1, 0, 1, g_hB, Cc, sm);
        groupbar(grp);
        gemm_tile_tc(g_hB, Cc, g_Wh + 1*Cc*Cc, Cc, m0, n0, Cc, h_b + 1*Cc, 1, 0, 1, g_hA, Cc, sm);
        groupbar(grp);
        gemm_tile_tc(g_hA, Cc, g_Wh + 2*Cc*Cc, Cc, m0, n0, Cc, h_b + 2*Cc, 1, 0, 1, g_hB, Cc, sm);
        groupbar(grp);

        // ── P6: WAIT for all pairwise, then median + out GEMV + update ──
        {
            if (tid == 0){
                unsigned long long target = (sm_hold/128ULL + 1ULL)*128ULL;
                while (*(volatile unsigned long long*)&g_hdone < target) { }
            }
            __syncthreads();
            __threadfence();

            float ht = median_local(g_hist[par], sm);
            float inv_ht = 1.f/ht;
            int p = tid >> 6;
            int d = tid & 63;
            int i = blk*4 + p;
            float dt = eps[0];
            float t = g_betas[s];
            float s2dt = sqrtf(2.f*dt);
            float xi_d = x[i*Dd + d];
            #pragma unroll
            for (int q = 0; q < 8; q++){
                int j = d + q*64;
                sm->u.w[p][j] = expf(-g_d2[i*Bp + j]*inv_ht);
            }
            if (d < MC){
                float sacc = 0.f;
                #pragma unroll 4
                for (int k = 0; k < Dd; k++){
                    float df = x[i*Dd + k] - means[d*Dd + k];
                    sacc += df*df;
                }
                sm->u.compm[p][d] = -0.5f*sacc;
            }
            __syncthreads();
            if (d == 0){
                float mx = sm->u.compm[p][0];
                for (int m = 1; m < MC; m++) mx = fmaxf(mx, sm->u.compm[p][m]);
                float se = 0.f;
                for (int m = 0; m < MC; m++){
                    float e = expf(sm->u.compm[p][m]-mx);
                    sm->u.wm[p][m] = e; se += e;
                }
                float inv = 1.f/se;
                for (int m = 0; m < MC; m++) sm->u.wm[p][m] *= inv;
            }
            __syncthreads();
            float wbar = 0.f;
            #pragma unroll
            for (int m = 0; m < MC; m++) wbar += sm->u.wm[p][m]*means[m*Dd + d];
            // repulsion over all 512 particles
            float r = 0.f;
            const float* wrow = sm->u.w[p];
            #pragma unroll 8
            for (int j = 0; j < Bp; j++)
                r += wrow[j]*(xi_d - x[j*Dd + d]);
            // final-layer GEMV for own particle (fp32, K=512)
            float sc = out_b[d];
            {
                const float* hb = g_hB + (size_t)i*Cc;
                #pragma unroll 8
                for (int k = 0; k < Cc; k++)
                    sc += hb[k]*out_W[k*Dd + d];
            }
            float drift = t*wbar - xi_d - sc;
            float nv = noises[((size_t)s*Bp + i)*Dd + d];
            xn[i*Dd + d] = xi_d + dt*drift + s2dt*nv + 0.1f*dt*inv_ht*r;
            // zero the OTHER histogram (used next step)
            for (int idx = gtid; idx < NBINS; idx += NT) g_hist[par^1][idx] = 0;
        }
        gridbar();   // next step's pairwise reads ALL new particles
    }
}

extern "C" void kernel_launch(void* const* d_in, const int* in_sizes, int n_in,
                              void* d_out, int out_size){
    const float* particles = (const float*)d_in[0];
    const float* noises    = (const float*)d_in[1];
    const float* grid_t    = (const float*)d_in[2];
    const float* eps       = (const float*)d_in[3];
    const float* means     = (const float*)d_in[4];
    const float* phase     = (const float*)d_in[5];
    const float* in_W      = (const float*)d_in[6];
    const float* in_b      = (const float*)d_in[7];
    const float* t_W1      = (const float*)d_in[8];
    const float* t_b1      = (const float*)d_in[9];
    const float* t_W2      = (const float*)d_in[10];
    const float* t_b2      = (const float*)d_in[11];
    const float* h_W       = (const float*)d_in[12];
    const float* h_b       = (const float*)d_in[13];
    const float* out_W     = (const float*)d_in[14];
    const float* out_b     = (const float*)d_in[15];
    float* out = (float*)d_out;

    static int smem_set = -1;
    int smem_bytes = (int)sizeof(Smem);
    if (smem_set < 0){
        cudaFuncSetAttribute(cmcd_fused, cudaFuncAttributeMaxDynamicSharedMemorySize, smem_bytes);
        smem_set = 1;
    }

    cmcd_fused<<<GRID, TPB, smem_bytes>>>(particles, noises, grid_t, eps, means, phase,
                                          in_W, in_b, t_W1, t_b1, t_W2, t_b2,
                                          h_W, h_b, out_W, out_b, out);
}

// round 12
// speedup vs baseline: 1.8529x; 1.8529x over previous
#include <cuda_runtime.h>
#include <math.h>

#define GRID 128
#define TPB  256
#define Bp   512
#define Dd   64
#define Cc   512
#define NBs  8
#define MC   8
#define NBINS 32768
#define BIN_SC ((float)NBINS/64.0f)
#define BPAD 16   // 16 ULL = 128B padding between barrier flags

__device__ float g_hA[Bp*Cc];
__device__ float g_hB[Bp*Cc];
__device__ float g_osp[16*Bp*Dd];     // out-layer partials per n-tile
__device__ float g_d2[Bp*Bp];
__device__ float g_temb[NBs*2*Cc];
__device__ float g_tg1[NBs*Cc];
__device__ float g_bias1[NBs*Cc];
__device__ float g_betas[NBs+1];
__device__ __align__(16) int g_hist[2][NBINS];
__device__ unsigned long long g_flags[GRID*BPAD];
__device__ unsigned long long g_epoch = 0ULL;
// weights pre-converted to tf32 bit patterns (stored as float bits)
__device__ float g_Win[Dd*Cc];
__device__ float g_Wh[3*Cc*Cc];
__device__ float g_Wout[Cc*Dd];

#define ASTR 36   // A smem row stride (floats): conflict-free frag loads
#define WSTR 40   // W smem row stride

struct SmG { float A[2][2][64*ASTR]; float W[2][2][32*WSTR]; float red[64*33]; };
struct SmP { float Xi[32*64]; float Xj[64*64]; };
struct SmU { float w[4][Bp]; float compm[4][MC]; float wm[4][MC]; };
struct SmM { int cnt[8]; int woff[8]; float v[2]; };
union Smem { SmG g; SmP p; SmU u; SmM m; };

__device__ __forceinline__ float gelu_t(float x){
    float x3 = x*x*x;
    return 0.5f*x*(1.0f+tanhf(0.7978845608028654f*(x+0.044715f*x3)));
}

__device__ __forceinline__ unsigned f2tf(float x){
    unsigned u;
    asm("cvt.rna.tf32.f32 %0, %1;" : "=r"(u) : "f"(x));
    return u;
}
__device__ __forceinline__ float f2tf_f(float x){ return __uint_as_float(f2tf(x)); }

__device__ __forceinline__ void mma_tf32(float* acc,
    unsigned a0, unsigned a1, unsigned a2, unsigned a3,
    unsigned b0, unsigned b1)
{
    asm volatile(
        "mma.sync.aligned.m16n8k8.row.col.f32.tf32.tf32.f32 "
        "{%0,%1,%2,%3}, {%4,%5,%6,%7}, {%8,%9}, {%0,%1,%2,%3};"
        : "+f"(acc[0]), "+f"(acc[1]), "+f"(acc[2]), "+f"(acc[3])
        : "r"(a0), "r"(a1), "r"(a2), "r"(a3), "r"(b0), "r"(b1));
}

// flag/epoch grid barrier: no serialized atomics. Monotone across replays.
__device__ __forceinline__ void gridbar2(int blk, int tid, unsigned long long target){
    __threadfence();
    __syncthreads();
    if (tid == 0)
        *((volatile unsigned long long*)&g_flags[blk*BPAD]) = target;
    if (blk == 0){
        if (tid < GRID){
            while (*((volatile unsigned long long*)&g_flags[tid*BPAD]) < target)
                __nanosleep(40);
        }
        __syncthreads();
        __threadfence();
        if (tid == 0)
            *((volatile unsigned long long*)&g_epoch) = target;
    }
    if (tid == 0){
        while (*((volatile unsigned long long*)&g_epoch) < target)
            __nanosleep(40);
    }
    __syncthreads();
    __threadfence();
}

#define GB() do { ecnt++; gridbar2(blk, tid, ebase + ecnt); } while(0)

// one 64x32 output tile of C = act(A@W + bias) via tf32 tensor cores.
// 256 threads, 2-way K-split. W holds tf32 bit patterns. Activations stored
// tf32-rounded. fold: also multiply own tile by out_W rows [n0,n0+32) into
// fold_out (out-layer partial for this n-tile).
__device__ __forceinline__ void gemm_tile_tc(
    const float* __restrict__ A, int Astr, const float* __restrict__ W, int Wstr,
    int m0, int n0, int klen,
    const float* __restrict__ bias, int act, int convA,
    int fold, float* __restrict__ fold_out,
    float* __restrict__ C, int Cstr, Smem* sm)
{
    int tid  = threadIdx.x;
    int gid  = tid >> 7;            // K-split group (0/1)
    int tg   = tid & 127;
    int warp = tg >> 5, lane = tid & 31;
    int g = lane >> 2, t = lane & 3;

    int arow = tg >> 1;             // 0..63
    int kseg = (tg & 1) * 16;       // 0 or 16
    int wk   = tg >> 2;             // 0..31
    int nseg = (tg & 3) * 8;        // 0,8,16,24

    int khalf = klen >> 1;
    int kb0   = gid*khalf;
    int NC    = khalf >> 5;

    float acc[4][4] = {};
    float4 ra[4], rw[2];

    #pragma unroll
    for (int q = 0; q < 4; q++)
        ra[q] = *(const float4*)&A[(size_t)(m0+arow)*Astr + kb0 + kseg + 4*q];
    #pragma unroll
    for (int q = 0; q < 2; q++)
        rw[q] = *(const float4*)&W[(size_t)(kb0+wk)*Wstr + n0 + nseg + 4*q];
    if (convA){
        #pragma unroll
        for (int q = 0; q < 4; q++){
            ra[q].x = f2tf_f(ra[q].x); ra[q].y = f2tf_f(ra[q].y);
            ra[q].z = f2tf_f(ra[q].z); ra[q].w = f2tf_f(ra[q].w);
        }
    }
    {
        float* As = sm->g.A[gid][0]; float* Ws = sm->g.W[gid][0];
        #pragma unroll
        for (int q = 0; q < 4; q++) *(float4*)&As[arow*ASTR + kseg + 4*q] = ra[q];
        #pragma unroll
        for (int q = 0; q < 2; q++) *(float4*)&Ws[wk*WSTR + nseg + 4*q] = rw[q];
    }

    for (int c = 0; c < NC; c++){
        __syncthreads();
        int cb = c & 1;
        if (c+1 < NC){
            int kb = kb0 + (c+1)*32;
            #pragma unroll
            for (int q = 0; q < 4; q++)
                ra[q] = *(const float4*)&A[(size_t)(m0+arow)*Astr + kb + kseg + 4*q];
            #pragma unroll
            for (int q = 0; q < 2; q++)
                rw[q] = *(const float4*)&W[(size_t)(kb+wk)*Wstr + n0 + nseg + 4*q];
            if (convA){
                #pragma unroll
                for (int q = 0; q < 4; q++){
                    ra[q].x = f2tf_f(ra[q].x); ra[q].y = f2tf_f(ra[q].y);
                    ra[q].z = f2tf_f(ra[q].z); ra[q].w = f2tf_f(ra[q].w);
                }
            }
        }
        const float* As = sm->g.A[gid][cb];
        const float* Ws = sm->g.W[gid][cb];
        #pragma unroll
        for (int kk = 0; kk < 4; kk++){
            int ab = (16*warp + g)*ASTR + kk*8;
            unsigned a0 = __float_as_uint(As[ab + t]);
            unsigned a1 = __float_as_uint(As[ab + 8*ASTR + t]);
            unsigned a2 = __float_as_uint(As[ab + t + 4]);
            unsigned a3 = __float_as_uint(As[ab + 8*ASTR + t + 4]);
            #pragma unroll
            for (int c4 = 0; c4 < 4; c4++){
                unsigned b0 = __float_as_uint(Ws[(kk*8 + t)*WSTR + c4*8 + g]);
                unsigned b1 = __float_as_uint(Ws[(kk*8 + t + 4)*WSTR + c4*8 + g]);
                mma_tf32(acc[c4], a0, a1, a2, a3, b0, b1);
            }
        }
        if (c+1 < NC){
            int nb = cb ^ 1;
            float* As2 = sm->g.A[gid][nb]; float* Ws2 = sm->g.W[gid][nb];
            #pragma unroll
            for (int q = 0; q < 4; q++) *(float4*)&As2[arow*ASTR + kseg + 4*q] = ra[q];
            #pragma unroll
            for (int q = 0; q < 2; q++) *(float4*)&Ws2[wk*WSTR + nseg + 4*q] = rw[q];
        }
    }

    __syncthreads();
    int r0 = 16*warp + g;
    if (gid == 1){
        #pragma unroll
        for (int c4 = 0; c4 < 4; c4++){
            int col = c4*8 + 2*t;
            sm->g.red[r0*33 + col]       = acc[c4][0];
            sm->g.red[r0*33 + col + 1]   = acc[c4][1];
            sm->g.red[(r0+8)*33 + col]   = acc[c4][2];
            sm->g.red[(r0+8)*33 + col+1] = acc[c4][3];
        }
    }
    __syncthreads();
    if (gid == 0){
        #pragma unroll
        for (int c4 = 0; c4 < 4; c4++){
            int col = c4*8 + 2*t;
            float v00 = acc[c4][0] + sm->g.red[r0*33 + col];
            float v01 = acc[c4][1] + sm->g.red[r0*33 + col + 1];
            float v10 = acc[c4][2] + sm->g.red[(r0+8)*33 + col];
            float v11 = acc[c4][3] + sm->g.red[(r0+8)*33 + col+1];
            int n = n0 + col;
            if (bias){ v00 += bias[n]; v01 += bias[n+1]; v10 += bias[n]; v11 += bias[n+1]; }
            if (act){ v00 = gelu_t(v00); v01 = gelu_t(v01); v10 = gelu_t(v10); v11 = gelu_t(v11); }
            v00 = f2tf_f(v00); v01 = f2tf_f(v01); v10 = f2tf_f(v10); v11 = f2tf_f(v11);
            C[(size_t)(m0+r0)*Cstr + n]       = v00;
            C[(size_t)(m0+r0)*Cstr + n + 1]   = v01;
            C[(size_t)(m0+r0+8)*Cstr + n]     = v10;
            C[(size_t)(m0+r0+8)*Cstr + n + 1] = v11;
            if (fold){
                // overwrite red with the final rounded tile (each thread its own slots)
                sm->g.red[r0*33 + col]       = v00;
                sm->g.red[r0*33 + col + 1]   = v01;
                sm->g.red[(r0+8)*33 + col]   = v10;
                sm->g.red[(r0+8)*33 + col+1] = v11;
            }
        }
    }
    __syncthreads();

    if (fold){
        // tile[64m x 32k] @ out_W[n0+ :32k, 64d] -> fold_out[64m x 64d]
        int w8 = tid >> 5;
        int wm = w8 & 3, wn = w8 >> 2;
        float acc2[4][4] = {};
        #pragma unroll
        for (int kk = 0; kk < 4; kk++){
            int ab = (16*wm + g)*33 + kk*8;
            unsigned a0 = __float_as_uint(sm->g.red[ab + t]);
            unsigned a1 = __float_as_uint(sm->g.red[ab + 8*33 + t]);
            unsigned a2 = __float_as_uint(sm->g.red[ab + t + 4]);
            unsigned a3 = __float_as_uint(sm->g.red[ab + 8*33 + t + 4]);
            #pragma unroll
            for (int c4 = 0; c4 < 4; c4++){
                unsigned b0 = __float_as_uint(g_Wout[(size_t)(n0 + kk*8 + t)*Dd + 32*wn + c4*8 + g]);
                unsigned b1 = __float_as_uint(g_Wout[(size_t)(n0 + kk*8 + t + 4)*Dd + 32*wn + c4*8 + g]);
                mma_tf32(acc2[c4], a0, a1, a2, a3, b0, b1);
            }
        }
        #pragma unroll
        for (int c4 = 0; c4 < 4; c4++){
            int row = m0 + 16*wm + g;
            int dcol = 32*wn + c4*8 + 2*t;
            fold_out[(size_t)row*Dd + dcol]       = acc2[c4][0];
            fold_out[(size_t)row*Dd + dcol + 1]   = acc2[c4][1];
            fold_out[(size_t)(row+8)*Dd + dcol]   = acc2[c4][2];
            fold_out[(size_t)(row+8)*Dd + dcol+1] = acc2[c4][3];
        }
        __syncthreads();
    }
}

// 32x64 tile of pairwise squared distances + histogram (256 threads)
__device__ __forceinline__ void pairwise_tile(const float* __restrict__ x, int i0, int j0,
                                              int* __restrict__ hist, Smem* sm){
    int tid = threadIdx.x;
    #pragma unroll
    for (int q = 0; q < 2; q++){
        int idx = tid + 256*q;
        int r = idx>>4, c4 = (idx&15)*4;
        if (r < 32){
            float4 v = *(const float4*)&x[(i0+r)*Dd + c4];
            sm->p.Xi[(c4+0)*32+r]=v.x; sm->p.Xi[(c4+1)*32+r]=v.y;
            sm->p.Xi[(c4+2)*32+r]=v.z; sm->p.Xi[(c4+3)*32+r]=v.w;
        }
    }
    #pragma unroll
    for (int q = 0; q < 4; q++){
        int idx = tid + 256*q;
        int row = idx>>4, c4 = (idx&15)*4;
        float4 v = *(const float4*)&x[(j0+row)*Dd + c4];
        sm->p.Xj[(c4+0)*64+row]=v.x; sm->p.Xj[(c4+1)*64+row]=v.y;
        sm->p.Xj[(c4+2)*64+row]=v.z; sm->p.Xj[(c4+3)*64+row]=v.w;
    }
    __syncthreads();
    int ty = tid>>4, tx = tid&15;          // 16x16 thread grid, 2x4 micro
    float acc[2][4] = {};
    #pragma unroll
    for (int k = 0; k < 64; k++){
        float a0 = sm->p.Xi[k*32 + ty*2];
        float a1 = sm->p.Xi[k*32 + ty*2 + 1];
        float4 b = *(const float4*)&sm->p.Xj[k*64 + tx*4];
        float d;
        d=a0-b.x; acc[0][0]+=d*d;  d=a0-b.y; acc[0][1]+=d*d;
        d=a0-b.z; acc[0][2]+=d*d;  d=a0-b.w; acc[0][3]+=d*d;
        d=a1-b.x; acc[1][0]+=d*d;  d=a1-b.y; acc[1][1]+=d*d;
        d=a1-b.z; acc[1][2]+=d*d;  d=a1-b.w; acc[1][3]+=d*d;
    }
    #pragma unroll
    for (int i = 0; i < 2; i++){
        int gi = i0 + ty*2 + i;
        #pragma unroll
        for (int j = 0; j < 4; j++){
            int gj = j0 + tx*4 + j;
            float d2 = acc[i][j];
            g_d2[gi*Bp + gj] = d2;
            float dist = sqrtf(d2 > 0.f ? d2 : 1e-12f);
            int bin = (int)(dist*BIN_SC);
            if (bin > NBINS-1) bin = NBINS-1;
            atomicAdd(&hist[bin], 1);
        }
    }
    __syncthreads();
}

// exact median via warp-shuffle scan + warp-cooperative rank walk
__device__ __forceinline__ float median_local(const int* __restrict__ hist, Smem* sm){
    int tid = threadIdx.x, lane = tid & 31, warp = tid >> 5;
    const int per = NBINS/TPB;   // 128
    int ssum = 0;
    {
        const int4* h4 = (const int4*)(hist + tid*per);
        #pragma unroll 8
        for (int b = 0; b < per/4; b++){ int4 v = h4[b]; ssum += v.x+v.y+v.z+v.w; }
    }
    // warp inclusive scan
    int incl = ssum;
    #pragma unroll
    for (int o = 1; o < 32; o <<= 1){
        int n = __shfl_up_sync(0xffffffffu, incl, o);
        if (lane >= o) incl += n;
    }
    if (lane == 31) sm->m.cnt[warp] = incl;
    __syncthreads();
    if (warp == 0 && lane < 8){
        int v = sm->m.cnt[lane];
        int sacc = v;
        #pragma unroll
        for (int o = 1; o < 8; o <<= 1){
            int n = __shfl_up_sync(0xffu, sacc, o);
            if (lane >= o) sacc += n;
        }
        sm->m.woff[lane] = sacc - v;  // exclusive warp offset
    }
    __syncthreads();
    int cur  = sm->m.woff[warp] + incl;
    int prev = cur - ssum;
    const int k1 = Bp*Bp/2, k2 = Bp*Bp/2 + 1;
    #pragma unroll
    for (int q = 0; q < 2; q++){
        int kq = (q == 0) ? k1 : k2;
        unsigned msk = __ballot_sync(0xffffffffu, prev < kq && kq <= cur);
        if (msk){
            int src   = __ffs(msk) - 1;
            int pbase = __shfl_sync(0xffffffffu, prev, src);
            int cbase = (__shfl_sync(0xffffffffu, tid, src))*per;
            int4 v = *(const int4*)(hist + cbase + lane*4);
            int sl = v.x+v.y+v.z+v.w;
            int i2 = sl;
            #pragma unroll
            for (int o = 1; o < 32; o <<= 1){
                int n = __shfl_up_sync(0xffffffffu, i2, o);
                if (lane >= o) i2 += n;
            }
            int cumL = pbase + i2, prevL = cumL - sl;
            if (prevL < kq && kq <= cumL){
                int b = cbase + lane*4, c = prevL, bb;
                c += v.x; if (c >= kq) bb = b;
                else { c += v.y; if (c >= kq) bb = b+1;
                       else { c += v.z; if (c >= kq) bb = b+2; else bb = b+3; } }
                sm->m.v[q] = ((float)bb + 0.5f)/BIN_SC;
            }
        }
    }
    __syncthreads();
    float med = 0.5f*(sm->m.v[0] + sm->m.v[1]);
    float ht = med*med / logf((float)Bp);
    __syncthreads();     // everyone has read v[] before the union is reused
    return ht;
}

__global__ void __launch_bounds__(TPB, 1)
cmcd_fused(const float* __restrict__ particles, const float* __restrict__ noises,
           const float* __restrict__ grid_t, const float* __restrict__ eps,
           const float* __restrict__ means, const float* __restrict__ phase,
           const float* __restrict__ in_W, const float* __restrict__ in_b,
           const float* __restrict__ t_W1, const float* __restrict__ t_b1,
           const float* __restrict__ t_W2, const float* __restrict__ t_b2,
           const float* __restrict__ h_W, const float* __restrict__ h_b,
           const float* __restrict__ out_W, const float* __restrict__ out_b,
           float* __restrict__ out)
{
    extern __shared__ unsigned char smem_raw[];
    Smem* sm = reinterpret_cast<Smem*>(smem_raw);
    int blk = blockIdx.x, tid = threadIdx.x;
    int gtid = blk*TPB + tid;
    const int NT = GRID*TPB;

    unsigned long long ebase = *((volatile unsigned long long*)&g_epoch);
    unsigned long long ecnt = 0;

    // ── S0: copy slice 0, zero hists, temb, betas, tf32-convert weights ──
    for (int idx = gtid; idx < Bp*Dd; idx += NT) out[idx] = particles[idx];
    for (int idx = gtid; idx < 2*NBINS; idx += NT) g_hist[0][idx] = 0;
    for (int idx = gtid; idx < Dd*Cc; idx += NT) g_Win[idx] = f2tf_f(in_W[idx]);
    for (int idx = gtid; idx < 3*Cc*Cc; idx += NT) g_Wh[idx] = f2tf_f(h_W[idx]);
    for (int idx = gtid; idx < Cc*Dd; idx += NT) g_Wout[idx] = f2tf_f(out_W[idx]);
    for (int idx = gtid; idx < NBs*2*Cc; idx += NT){
        int s = idx >> 10, c = idx & 1023;
        float t = (float)s;
        int cc = (c < Cc) ? c : c - Cc;
        float coeff = 0.1f + (float)cc*(99.9f/511.0f);
        float e = coeff*t + phase[cc];
        g_temb[idx] = (c < Cc) ? sinf(e) : cosf(e);
    }
    if (gtid == 0){
        float cum = 0.f;
        g_betas[0] = 0.f;
        for (int j = 0; j < NBs; j++){
            float sg = 1.f/(1.f+expf(-grid_t[j]));
            cum += sg;
            g_betas[j+1] = cum;
        }
        float inv = 1.f/cum;
        for (int j = 1; j <= NBs; j++) g_betas[j] *= inv;
    }
    GB();

    // ── S1: t-MLP layer 1 (8-way K-split + shuffle reduce) ──
    {
        int oidx = gtid >> 3;       // 0..4095
        int sl   = gtid & 7;
        int s = oidx >> 9, c = oidx & 511;
        float acc = 0.f;
        const float* tb = g_temb + s*2*Cc;
        int kb = sl*128;
        #pragma unroll 4
        for (int k = kb; k < kb+128; k++) acc += tb[k]*t_W1[k*Cc + c];
        #pragma unroll
        for (int o = 1; o < 8; o <<= 1) acc += __shfl_xor_sync(0xffffffffu, acc, o);
        if (sl == 0) g_tg1[oidx] = gelu_t(acc + t_b1[c]);
    }
    GB();

    // ── S2: t-MLP layer 2 + in_b → fused input bias ──
    {
        int oidx = gtid >> 3;
        int sl   = gtid & 7;
        int s = oidx >> 9, c = oidx & 511;
        float acc = 0.f;
        const float* gb = g_tg1 + s*Cc;
        int kb = sl*64;
        #pragma unroll 4
        for (int k = kb; k < kb+64; k++) acc += gb[k]*t_W2[k*Cc + c];
        #pragma unroll
        for (int o = 1; o < 8; o <<= 1) acc += __shfl_xor_sync(0xffffffffu, acc, o);
        if (sl == 0) g_bias1[oidx] = acc + t_b2[c] + in_b[c];
    }
    GB();

    int m0 = (blk >> 4) * 64;     // 8 m-slabs of 64 rows
    int n0 = (blk & 15) * 32;     // 16 n-tiles of 32 cols
    float* fold_out = g_osp + (size_t)(blk & 15)*Bp*Dd;

    for (int s = 0; s < NBs; s++){
        const float* x = out + (size_t)s*Bp*Dd;
        float* xn      = out + (size_t)(s+1)*Bp*Dd;
        int par = s & 1;

        // ── P1: input layer (K=64, conv A) + pairwise d2/hist ──
        gemm_tile_tc(x, Dd, g_Win, Cc, m0, n0, Dd, g_bias1 + s*Cc, 1, 1, 0, nullptr, g_hA, Cc, sm);
        pairwise_tile(x, (blk>>3)*32, (blk&7)*64, g_hist[par], sm);
        GB();

        // ── P2-P4: hidden layers (P4 folds out-layer partials) ──
        gemm_tile_tc(g_hA, Cc, g_Wh + 0*Cc*Cc, Cc, m0, n0, Cc, h_b + 0*Cc, 1, 0, 0, nullptr, g_hB, Cc, sm);
        GB();
        gemm_tile_tc(g_hB, Cc, g_Wh + 1*Cc*Cc, Cc, m0, n0, Cc, h_b + 1*Cc, 1, 0, 0, nullptr, g_hA, Cc, sm);
        GB();
        gemm_tile_tc(g_hA, Cc, g_Wh + 2*Cc*Cc, Cc, m0, n0, Cc, h_b + 2*Cc, 1, 0, 1, fold_out, g_hB, Cc, sm);
        GB();

        // ── P6: median + update (score = sum of 16 out-layer partials) ──
        {
            float ht = median_local(g_hist[par], sm);
            float inv_ht = 1.f/ht;
            int p = tid >> 6;
            int d = tid & 63;
            int i = blk*4 + p;
            float dt = eps[0];
            float t = g_betas[s];
            float s2dt = sqrtf(2.f*dt);
            float xi_d = x[i*Dd + d];
            #pragma unroll
            for (int q = 0; q < 8; q++){
                int j = d + q*64;
                sm->u.w[p][j] = expf(-g_d2[i*Bp + j]*inv_ht);
            }
            if (d < MC){
                float sacc = 0.f;
                #pragma unroll 4
                for (int k = 0; k < Dd; k++){
                    float df = x[i*Dd + k] - means[d*Dd + k];
                    sacc += df*df;
                }
                sm->u.compm[p][d] = -0.5f*sacc;
            }
            __syncthreads();
            if (d == 0){
                float mx = sm->u.compm[p][0];
                for (int m = 1; m < MC; m++) mx = fmaxf(mx, sm->u.compm[p][m]);
                float se = 0.f;
                for (int m = 0; m < MC; m++){
                    float e = expf(sm->u.compm[p][m]-mx);
                    sm->u.wm[p][m] = e; se += e;
                }
                float inv = 1.f/se;
                for (int m = 0; m < MC; m++) sm->u.wm[p][m] *= inv;
            }
            __syncthreads();
            float wbar = 0.f;
            #pragma unroll
            for (int m = 0; m < MC; m++) wbar += sm->u.wm[p][m]*means[m*Dd + d];
            float r = 0.f;
            const float* wrow = sm->u.w[p];
            #pragma unroll 8
            for (int j = 0; j < Bp; j++)
                r += wrow[j]*(xi_d - x[j*Dd + d]);
            float sc = out_b[d];
            #pragma unroll
            for (int nt = 0; nt < 16; nt++)
                sc += g_osp[((size_t)nt*Bp + i)*Dd + d];
            float drift = t*wbar - xi_d - sc;
            float nv = noises[((size_t)s*Bp + i)*Dd + d];
            xn[i*Dd + d] = xi_d + dt*drift + s2dt*nv + 0.1f*dt*inv_ht*r;
            // zero the OTHER histogram (used next step)
            for (int idx = gtid; idx < NBINS; idx += NT) g_hist[par^1][idx] = 0;
        }
        GB();
    }
}

extern "C" void kernel_launch(void* const* d_in, const int* in_sizes, int n_in,
                              void* d_out, int out_size){
    const float* particles = (const float*)d_in[0];
    const float* noises    = (const float*)d_in[1];
    const float* grid_t    = (const float*)d_in[2];
    const float* eps       = (const float*)d_in[3];
    const float* means     = (const float*)d_in[4];
    const float* phase     = (const float*)d_in[5];
    const float* in_W      = (const float*)d_in[6];
    const float* in_b      = (const float*)d_in[7];
    const float* t_W1      = (const float*)d_in[8];
    const float* t_b1      = (const float*)d_in[9];
    const float* t_W2      = (const float*)d_in[10];
    const float* t_b2      = (const float*)d_in[11];
    const float* h_W       = (const float*)d_in[12];
    const float* h_b       = (const float*)d_in[13];
    const float* out_W     = (const float*)d_in[14];
    const float* out_b     = (const float*)d_in[15];
    float* out = (float*)d_out;

    static int smem_set = -1;
    int smem_bytes = (int)sizeof(Smem);
    if (smem_set < 0){
        cudaFuncSetAttribute(cmcd_fused, cudaFuncAttributeMaxDynamicSharedMemorySize, smem_bytes);
        smem_set = 1;
    }

    cmcd_fused<<<GRID, TPB, smem_bytes>>>(particles, noises, grid_t, eps, means, phase,
                                          in_W, in_b, t_W1, t_b1, t_W2, t_b2,
                                          h_W, h_b, out_W, out_b, out);
}

// round 13
// speedup vs baseline: 2.2414x; 1.2096x over previous
#include <cuda_runtime.h>
#include <cuda_bf16.h>
#include <math.h>

#define GRID 128
#define TPB  256
#define Bp   512
#define Dd   64
#define Cc   512
#define NBs  8
#define MC   8
#define NBINS 32768
#define BIN_SC ((float)NBINS/64.0f)
#define BPAD 16

__device__ __nv_bfloat16 g_hA[Bp*Cc];
__device__ __nv_bfloat16 g_hB[Bp*Cc];
__device__ float g_osp[16*Bp*Dd];     // out-layer partials per n-tile
__device__ float g_d2[Bp*Bp];
__device__ float g_temb[NBs*2*Cc];
__device__ float g_tg1[NBs*Cc];
__device__ float g_bias1[NBs*Cc];
__device__ float g_betas[NBs+1];
__device__ __align__(16) int g_hist[2][NBINS];
__device__ unsigned long long g_flags[GRID*BPAD];
__device__ unsigned long long g_epoch = 0ULL;
// weights transposed to [n][k] and converted to bf16 at setup
__device__ __nv_bfloat16 g_WinT[Cc*Dd];      // [n=Cc][k=Dd]
__device__ __nv_bfloat16 g_WhT[3*Cc*Cc];     // [l][n][k]
__device__ __nv_bfloat16 g_WoutT[Dd*Cc];     // [d][k]

#define SA 40    // smem half-stride (conflict-free frag loads: bank 4g+t style)
#define SX 520   // P6 X/A stride (260 mod 32 == 4)

struct SmG {
    __nv_bfloat16 A[2][2][64*SA];
    __nv_bfloat16 W[2][2][32*SA];
    float redf[64*33];
    __nv_bfloat16 redh[64*SA];
};
struct SmP { float Xi[32*64]; float Xj[64*64]; };
struct SmU {
    __nv_bfloat16 Xt[64*SX];   // x transposed [d][j] bf16
    __nv_bfloat16 Aw[16*SX];   // w matrix [m(16 pad)][j] bf16
    float T[4*64];
    float S[4];
    float wm[4][MC];
};
struct SmM { int cnt[8]; int woff[8]; float v[2]; };
union Smem { SmG g; SmP p; SmU u; SmM m; };

__device__ __forceinline__ float gelu_t(float x){
    float x3 = x*x*x;
    return 0.5f*x*(1.0f+tanhf(0.7978845608028654f*(x+0.044715f*x3)));
}

// pack two floats to bf16x2 (lo in low half)
__device__ __forceinline__ unsigned bf2(float lo, float hi){
    unsigned r;
    asm("cvt.rn.bf16x2.f32 %0, %1, %2;" : "=r"(r) : "f"(hi), "f"(lo));
    return r;
}

__device__ __forceinline__ void mma_bf16(float* acc,
    unsigned a0, unsigned a1, unsigned a2, unsigned a3,
    unsigned b0, unsigned b1)
{
    asm volatile(
        "mma.sync.aligned.m16n8k16.row.col.f32.bf16.bf16.f32 "
        "{%0,%1,%2,%3}, {%4,%5,%6,%7}, {%8,%9}, {%0,%1,%2,%3};"
        : "+f"(acc[0]), "+f"(acc[1]), "+f"(acc[2]), "+f"(acc[3])
        : "r"(a0), "r"(a1), "r"(a2), "r"(a3), "r"(b0), "r"(b1));
}

// flag/epoch grid barrier: no serialized atomics. Monotone across replays.
__device__ __forceinline__ void gridbar2(int blk, int tid, unsigned long long target){
    __threadfence();
    __syncthreads();
    if (tid == 0)
        *((volatile unsigned long long*)&g_flags[blk*BPAD]) = target;
    if (blk == 0){
        if (tid < GRID){
            while (*((volatile unsigned long long*)&g_flags[tid*BPAD]) < target)
                __nanosleep(32);
        }
        __syncthreads();
        __threadfence();
        if (tid == 0)
            *((volatile unsigned long long*)&g_epoch) = target;
    }
    if (tid == 0){
        while (*((volatile unsigned long long*)&g_epoch) < target) { }
    }
    __syncthreads();
    __threadfence();
}

#define GB() do { ecnt++; gridbar2(blk, tid, ebase + ecnt); } while(0)

// one 64x32 output tile of C = act(A@W + bias) via bf16 tensor cores.
// 256 threads, 2-way K-split. WT is [n][k] bf16. C stored bf16.
// convA: A is fp32 (x), converted during staging.
// fold: also multiply own (rounded) tile by out_W rows [n0,n0+32) into fold_out.
__device__ __forceinline__ void gemm_bf16(
    const void* Aptr, int Astr, int convA,
    const __nv_bfloat16* __restrict__ WT, int Wstr,
    int m0, int n0, int klen,
    const float* __restrict__ bias, int act,
    int fold, float* __restrict__ fold_out,
    __nv_bfloat16* __restrict__ C, int Cstr, Smem* sm)
{
    int tid  = threadIdx.x;
    int gid  = tid >> 7;
    int tg   = tid & 127;
    int warp = tg >> 5, lane = tid & 31;
    int g = lane >> 2, t = lane & 3;

    int arow = tg >> 1, kseg = (tg & 1)*16;   // A: 16 halves per thread
    int wn   = tg >> 2, kofs = (tg & 3)*8;    // W: 8 halves per thread

    int khalf = klen >> 1;
    int kb0   = gid*khalf;
    int NC    = khalf >> 5;      // 32-k chunks

    float acc[4][4] = {};
    uint4 ua, ub, uw;

    // prologue: chunk 0
    {
        int kb = kb0;
        if (convA){
            const float* Af = (const float*)Aptr;
            const float* ap = &Af[(size_t)(m0+arow)*Astr + kb + kseg];
            float4 f0 = *(const float4*)ap,     f1 = *(const float4*)(ap+4);
            float4 f2 = *(const float4*)(ap+8), f3 = *(const float4*)(ap+12);
            ua.x = bf2(f0.x,f0.y); ua.y = bf2(f0.z,f0.w);
            ua.z = bf2(f1.x,f1.y); ua.w = bf2(f1.z,f1.w);
            ub.x = bf2(f2.x,f2.y); ub.y = bf2(f2.z,f2.w);
            ub.z = bf2(f3.x,f3.y); ub.w = bf2(f3.z,f3.w);
        } else {
            const __nv_bfloat16* Ah = (const __nv_bfloat16*)Aptr;
            const __nv_bfloat16* ap = &Ah[(size_t)(m0+arow)*Astr + kb + kseg];
            ua = *(const uint4*)ap; ub = *(const uint4*)(ap+8);
        }
        uw = *(const uint4*)&WT[(size_t)(n0+wn)*Wstr + kb + kofs];
        __nv_bfloat16* As = sm->g.A[gid][0];
        __nv_bfloat16* Ws = sm->g.W[gid][0];
        *(uint4*)&As[arow*SA + kseg]     = ua;
        *(uint4*)&As[arow*SA + kseg + 8] = ub;
        *(uint4*)&Ws[wn*SA + kofs]       = uw;
    }

    for (int c = 0; c < NC; c++){
        __syncthreads();
        int cb = c & 1;
        if (c+1 < NC){
            int kb = kb0 + (c+1)*32;
            if (convA){
                const float* Af = (const float*)Aptr;
                const float* ap = &Af[(size_t)(m0+arow)*Astr + kb + kseg];
                float4 f0 = *(const float4*)ap,     f1 = *(const float4*)(ap+4);
                float4 f2 = *(const float4*)(ap+8), f3 = *(const float4*)(ap+12);
                ua.x = bf2(f0.x,f0.y); ua.y = bf2(f0.z,f0.w);
                ua.z = bf2(f1.x,f1.y); ua.w = bf2(f1.z,f1.w);
                ub.x = bf2(f2.x,f2.y); ub.y = bf2(f2.z,f2.w);
                ub.z = bf2(f3.x,f3.y); ub.w = bf2(f3.z,f3.w);
            } else {
                const __nv_bfloat16* Ah = (const __nv_bfloat16*)Aptr;
                const __nv_bfloat16* ap = &Ah[(size_t)(m0+arow)*Astr + kb + kseg];
                ua = *(const uint4*)ap; ub = *(const uint4*)(ap+8);
            }
            uw = *(const uint4*)&WT[(size_t)(n0+wn)*Wstr + kb + kofs];
        }
        const __nv_bfloat16* As = sm->g.A[gid][cb];
        const __nv_bfloat16* Ws = sm->g.W[gid][cb];
        #pragma unroll
        for (int kk = 0; kk < 2; kk++){
            int ab = (16*warp + g)*SA + kk*16 + 2*t;
            unsigned a0 = *(const unsigned*)&As[ab];
            unsigned a1 = *(const unsigned*)&As[ab + 8*SA];
            unsigned a2 = *(const unsigned*)&As[ab + 8];
            unsigned a3 = *(const unsigned*)&As[ab + 8*SA + 8];
            #pragma unroll
            for (int c4 = 0; c4 < 4; c4++){
                int bb = (c4*8 + g)*SA + kk*16 + 2*t;
                unsigned b0 = *(const unsigned*)&Ws[bb];
                unsigned b1 = *(const unsigned*)&Ws[bb + 8];
                mma_bf16(acc[c4], a0, a1, a2, a3, b0, b1);
            }
        }
        if (c+1 < NC){
            int nb = cb ^ 1;
            __nv_bfloat16* As2 = sm->g.A[gid][nb];
            __nv_bfloat16* Ws2 = sm->g.W[gid][nb];
            *(uint4*)&As2[arow*SA + kseg]     = ua;
            *(uint4*)&As2[arow*SA + kseg + 8] = ub;
            *(uint4*)&Ws2[wn*SA + kofs]       = uw;
        }
    }

    __syncthreads();
    int r0 = 16*warp + g;
    if (gid == 1){
        #pragma unroll
        for (int c4 = 0; c4 < 4; c4++){
            int col = c4*8 + 2*t;
            sm->g.redf[r0*33 + col]       = acc[c4][0];
            sm->g.redf[r0*33 + col + 1]   = acc[c4][1];
            sm->g.redf[(r0+8)*33 + col]   = acc[c4][2];
            sm->g.redf[(r0+8)*33 + col+1] = acc[c4][3];
        }
    }
    __syncthreads();
    if (gid == 0){
        #pragma unroll
        for (int c4 = 0; c4 < 4; c4++){
            int col = c4*8 + 2*t;
            float v00 = acc[c4][0] + sm->g.redf[r0*33 + col];
            float v01 = acc[c4][1] + sm->g.redf[r0*33 + col + 1];
            float v10 = acc[c4][2] + sm->g.redf[(r0+8)*33 + col];
            float v11 = acc[c4][3] + sm->g.redf[(r0+8)*33 + col+1];
            int n = n0 + col;
            if (bias){ v00 += bias[n]; v01 += bias[n+1]; v10 += bias[n]; v11 += bias[n+1]; }
            if (act){ v00 = gelu_t(v00); v01 = gelu_t(v01); v10 = gelu_t(v10); v11 = gelu_t(v11); }
            unsigned pv0 = bf2(v00, v01);
            unsigned pv1 = bf2(v10, v11);
            *(unsigned*)&C[(size_t)(m0+r0)*Cstr + n]   = pv0;
            *(unsigned*)&C[(size_t)(m0+r0+8)*Cstr + n] = pv1;
            if (fold){
                *(unsigned*)&sm->g.redh[r0*SA + col]     = pv0;
                *(unsigned*)&sm->g.redh[(r0+8)*SA + col] = pv1;
            }
        }
    }
    __syncthreads();

    if (fold){
        // tile[64m x 32k] @ out_W^T -> fold_out[64m x 64d]
        int w8 = tid >> 5;
        int wm = w8 & 3, wn2 = w8 >> 2;
        float acc2[4][4] = {};
        const __nv_bfloat16* R = sm->g.redh;
        #pragma unroll
        for (int kk = 0; kk < 2; kk++){
            int ab = (16*wm + g)*SA + kk*16 + 2*t;
            unsigned a0 = *(const unsigned*)&R[ab];
            unsigned a1 = *(const unsigned*)&R[ab + 8*SA];
            unsigned a2 = *(const unsigned*)&R[ab + 8];
            unsigned a3 = *(const unsigned*)&R[ab + 8*SA + 8];
            #pragma unroll
            for (int c4 = 0; c4 < 4; c4++){
                const __nv_bfloat16* wp =
                    &g_WoutT[(size_t)(32*wn2 + c4*8 + g)*Cc + n0 + kk*16 + 2*t];
                unsigned b0 = *(const unsigned*)wp;
                unsigned b1 = *(const unsigned*)(wp + 8);
                mma_bf16(acc2[c4], a0, a1, a2, a3, b0, b1);
            }
        }
        #pragma unroll
        for (int c4 = 0; c4 < 4; c4++){
            int row = m0 + 16*wm + g;
            int dcol = 32*wn2 + c4*8 + 2*t;
            fold_out[(size_t)row*Dd + dcol]       = acc2[c4][0];
            fold_out[(size_t)row*Dd + dcol + 1]   = acc2[c4][1];
            fold_out[(size_t)(row+8)*Dd + dcol]   = acc2[c4][2];
            fold_out[(size_t)(row+8)*Dd + dcol+1] = acc2[c4][3];
        }
        __syncthreads();
    }
}

// 32x64 tile of pairwise squared distances + histogram (256 threads)
__device__ __forceinline__ void pairwise_tile(const float* __restrict__ x, int i0, int j0,
                                              int* __restrict__ hist, Smem* sm){
    int tid = threadIdx.x;
    #pragma unroll
    for (int q = 0; q < 2; q++){
        int idx = tid + 256*q;
        int r = idx>>4, c4 = (idx&15)*4;
        if (r < 32){
            float4 v = *(const float4*)&x[(i0+r)*Dd + c4];
            sm->p.Xi[(c4+0)*32+r]=v.x; sm->p.Xi[(c4+1)*32+r]=v.y;
            sm->p.Xi[(c4+2)*32+r]=v.z; sm->p.Xi[(c4+3)*32+r]=v.w;
        }
    }
    #pragma unroll
    for (int q = 0; q < 4; q++){
        int idx = tid + 256*q;
        int row = idx>>4, c4 = (idx&15)*4;
        float4 v = *(const float4*)&x[(j0+row)*Dd + c4];
        sm->p.Xj[(c4+0)*64+row]=v.x; sm->p.Xj[(c4+1)*64+row]=v.y;
        sm->p.Xj[(c4+2)*64+row]=v.z; sm->p.Xj[(c4+3)*64+row]=v.w;
    }
    __syncthreads();
    int ty = tid>>4, tx = tid&15;
    float acc[2][4] = {};
    #pragma unroll
    for (int k = 0; k < 64; k++){
        float a0 = sm->p.Xi[k*32 + ty*2];
        float a1 = sm->p.Xi[k*32 + ty*2 + 1];
        float4 b = *(const float4*)&sm->p.Xj[k*64 + tx*4];
        float d;
        d=a0-b.x; acc[0][0]+=d*d;  d=a0-b.y; acc[0][1]+=d*d;
        d=a0-b.z; acc[0][2]+=d*d;  d=a0-b.w; acc[0][3]+=d*d;
        d=a1-b.x; acc[1][0]+=d*d;  d=a1-b.y; acc[1][1]+=d*d;
        d=a1-b.z; acc[1][2]+=d*d;  d=a1-b.w; acc[1][3]+=d*d;
    }
    #pragma unroll
    for (int i = 0; i < 2; i++){
        int gi = i0 + ty*2 + i;
        #pragma unroll
        for (int j = 0; j < 4; j++){
            int gj = j0 + tx*4 + j;
            float d2 = acc[i][j];
            g_d2[gi*Bp + gj] = d2;
            float dist = sqrtf(d2 > 0.f ? d2 : 1e-12f);
            int bin = (int)(dist*BIN_SC);
            if (bin > NBINS-1) bin = NBINS-1;
            atomicAdd(&hist[bin], 1);
        }
    }
    __syncthreads();
}

// exact median via warp-shuffle scan + warp-cooperative rank walk
__device__ __forceinline__ float median_local(const int* __restrict__ hist, Smem* sm){
    int tid = threadIdx.x, lane = tid & 31, warp = tid >> 5;
    const int per = NBINS/TPB;   // 128
    int ssum = 0;
    {
        const int4* h4 = (const int4*)(hist + tid*per);
        #pragma unroll 8
        for (int b = 0; b < per/4; b++){ int4 v = h4[b]; ssum += v.x+v.y+v.z+v.w; }
    }
    int incl = ssum;
    #pragma unroll
    for (int o = 1; o < 32; o <<= 1){
        int n = __shfl_up_sync(0xffffffffu, incl, o);
        if (lane >= o) incl += n;
    }
    if (lane == 31) sm->m.cnt[warp] = incl;
    __syncthreads();
    if (warp == 0 && lane < 8){
        int v = sm->m.cnt[lane];
        int sacc = v;
        #pragma unroll
        for (int o = 1; o < 8; o <<= 1){
            int n = __shfl_up_sync(0xffu, sacc, o);
            if (lane >= o) sacc += n;
        }
        sm->m.woff[lane] = sacc - v;
    }
    __syncthreads();
    int cur  = sm->m.woff[warp] + incl;
    int prev = cur - ssum;
    const int k1 = Bp*Bp/2, k2 = Bp*Bp/2 + 1;
    #pragma unroll
    for (int q = 0; q < 2; q++){
        int kq = (q == 0) ? k1 : k2;
        unsigned msk = __ballot_sync(0xffffffffu, prev < kq && kq <= cur);
        if (msk){
            int src   = __ffs(msk) - 1;
            int pbase = __shfl_sync(0xffffffffu, prev, src);
            int cbase = (__shfl_sync(0xffffffffu, tid, src))*per;
            int4 v = *(const int4*)(hist + cbase + lane*4);
            int sl = v.x+v.y+v.z+v.w;
            int i2 = sl;
            #pragma unroll
            for (int o = 1; o < 32; o <<= 1){
                int n = __shfl_up_sync(0xffffffffu, i2, o);
                if (lane >= o) i2 += n;
            }
            int cumL = pbase + i2, prevL = cumL - sl;
            if (prevL < kq && kq <= cumL){
                int b = cbase + lane*4, c = prevL, bb;
                c += v.x; if (c >= kq) bb = b;
                else { c += v.y; if (c >= kq) bb = b+1;
                       else { c += v.z; if (c >= kq) bb = b+2; else bb = b+3; } }
                sm->m.v[q] = ((float)bb + 0.5f)/BIN_SC;
            }
        }
    }
    __syncthreads();
    float med = 0.5f*(sm->m.v[0] + sm->m.v[1]);
    float ht = med*med / logf((float)Bp);
    __syncthreads();
    return ht;
}

__global__ void __launch_bounds__(TPB, 1)
cmcd_fused(const float* __restrict__ particles, const float* __restrict__ noises,
           const float* __restrict__ grid_t, const float* __restrict__ eps,
           const float* __restrict__ means, const float* __restrict__ phase,
           const float* __restrict__ in_W, const float* __restrict__ in_b,
           const float* __restrict__ t_W1, const float* __restrict__ t_b1,
           const float* __restrict__ t_W2, const float* __restrict__ t_b2,
           const float* __restrict__ h_W, const float* __restrict__ h_b,
           const float* __restrict__ out_W, const float* __restrict__ out_b,
           float* __restrict__ out)
{
    extern __shared__ unsigned char smem_raw[];
    Smem* sm = reinterpret_cast<Smem*>(smem_raw);
    int blk = blockIdx.x, tid = threadIdx.x;
    int gtid = blk*TPB + tid;
    const int NT = GRID*TPB;

    unsigned long long ebase = *((volatile unsigned long long*)&g_epoch);
    unsigned long long ecnt = 0;

    // ── S0: copy slice 0, zero hists, temb, betas, transposed bf16 weights ──
    for (int idx = gtid; idx < Bp*Dd; idx += NT) out[idx] = particles[idx];
    for (int idx = gtid; idx < 2*NBINS; idx += NT) g_hist[0][idx] = 0;
    for (int idx = gtid; idx < Cc*Dd; idx += NT){
        int n = idx & 511, k = idx >> 9;
        g_WinT[n*Dd + k] = __float2bfloat16(in_W[k*Cc + n]);
    }
    for (int idx = gtid; idx < 3*Cc*Cc; idx += NT){
        int l = idx >> 18, r = idx & 262143;
        int n = r & 511, k = r >> 9;
        g_WhT[l*262144 + n*Cc + k] = __float2bfloat16(h_W[l*262144 + k*Cc + n]);
    }
    for (int idx = gtid; idx < Cc*Dd; idx += NT){
        int d = idx & 63, k = idx >> 6;
        g_WoutT[d*Cc + k] = __float2bfloat16(out_W[k*Dd + d]);
    }
    for (int idx = gtid; idx < NBs*2*Cc; idx += NT){
        int s = idx >> 10, c = idx & 1023;
        float t = (float)s;
        int cc = (c < Cc) ? c : c - Cc;
        float coeff = 0.1f + (float)cc*(99.9f/511.0f);
        float e = coeff*t + phase[cc];
        g_temb[idx] = (c < Cc) ? sinf(e) : cosf(e);
    }
    if (gtid == 0){
        float cum = 0.f;
        g_betas[0] = 0.f;
        for (int j = 0; j < NBs; j++){
            float sg = 1.f/(1.f+expf(-grid_t[j]));
            cum += sg;
            g_betas[j+1] = cum;
        }
        float inv = 1.f/cum;
        for (int j = 1; j <= NBs; j++) g_betas[j] *= inv;
    }
    GB();

    // ── S1: t-MLP layer 1 (8-way K-split + shuffle reduce) ──
    {
        int oidx = gtid >> 3;
        int sl   = gtid & 7;
        int s = oidx >> 9, c = oidx & 511;
        float acc = 0.f;
        const float* tb = g_temb + s*2*Cc;
        int kb = sl*128;
        #pragma unroll 4
        for (int k = kb; k < kb+128; k++) acc += tb[k]*t_W1[k*Cc + c];
        #pragma unroll
        for (int o = 1; o < 8; o <<= 1) acc += __shfl_xor_sync(0xffffffffu, acc, o);
        if (sl == 0) g_tg1[oidx] = gelu_t(acc + t_b1[c]);
    }
    GB();

    // ── S2: t-MLP layer 2 + in_b → fused input bias ──
    {
        int oidx = gtid >> 3;
        int sl   = gtid & 7;
        int s = oidx >> 9, c = oidx & 511;
        float acc = 0.f;
        const float* gb = g_tg1 + s*Cc;
        int kb = sl*64;
        #pragma unroll 4
        for (int k = kb; k < kb+64; k++) acc += gb[k]*t_W2[k*Cc + c];
        #pragma unroll
        for (int o = 1; o < 8; o <<= 1) acc += __shfl_xor_sync(0xffffffffu, acc, o);
        if (sl == 0) g_bias1[oidx] = acc + t_b2[c] + in_b[c];
    }
    GB();

    int m0 = (blk >> 4) * 64;
    int n0 = (blk & 15) * 32;
    float* fold_out = g_osp + (size_t)(blk & 15)*Bp*Dd;

    for (int s = 0; s < NBs; s++){
        const float* x = out + (size_t)s*Bp*Dd;
        float* xn      = out + (size_t)(s+1)*Bp*Dd;
        int par = s & 1;

        // ── P1: input layer (K=64, fp32 x converted) + pairwise d2/hist ──
        gemm_bf16(x, Dd, 1, g_WinT, Dd, m0, n0, Dd, g_bias1 + s*Cc, 1, 0, nullptr, g_hA, Cc, sm);
        pairwise_tile(x, (blk>>3)*32, (blk&7)*64, g_hist[par], sm);
        GB();

        // ── P2-P4: hidden layers (P4 folds out-layer partials) ──
        gemm_bf16(g_hA, Cc, 0, g_WhT + 0*Cc*Cc, Cc, m0, n0, Cc, h_b + 0*Cc, 1, 0, nullptr, g_hB, Cc, sm);
        GB();
        gemm_bf16(g_hB, Cc, 0, g_WhT + 1*Cc*Cc, Cc, m0, n0, Cc, h_b + 1*Cc, 1, 0, nullptr, g_hA, Cc, sm);
        GB();
        gemm_bf16(g_hA, Cc, 0, g_WhT + 2*Cc*Cc, Cc, m0, n0, Cc, h_b + 2*Cc, 1, 1, fold_out, g_hB, Cc, sm);
        GB();

        // ── P6: median + tensorized repulsion + update ──
        {
            float ht = median_local(g_hist[par], sm);
            float inv_ht = 1.f/ht;
            int lane = tid & 31;
            int p = tid >> 6;
            int d = tid & 63;
            int i = blk*4 + p;

            // stage x transposed as bf16: Xt[d][j]
            for (int it = tid; it < 8192; it += TPB){
                int j = it >> 4, d4 = (it & 15)*4;
                float4 v = *(const float4*)&x[j*Dd + d4];
                sm->u.Xt[(d4+0)*SX + j] = __float2bfloat16(v.x);
                sm->u.Xt[(d4+1)*SX + j] = __float2bfloat16(v.y);
                sm->u.Xt[(d4+2)*SX + j] = __float2bfloat16(v.z);
                sm->u.Xt[(d4+3)*SX + j] = __float2bfloat16(v.w);
            }
            // zero pad rows 4..15 of Aw
            for (int it = tid; it < 12*SX/2; it += TPB)
                ((unsigned*)(sm->u.Aw + 4*SX))[it] = 0;
            if (tid < 4) sm->u.S[tid] = 0.f;
            __syncthreads();

            // RBF weights -> Aw row p (bf16), and S[p] = sum of bf16 w
            float sw = 0.f;
            #pragma unroll
            for (int q = 0; q < 8; q++){
                int j = d + q*64;
                float wv = expf(-g_d2[i*Bp + j]*inv_ht);
                __nv_bfloat16 wb = __float2bfloat16(wv);
                sm->u.Aw[p*SX + j] = wb;
                sw += __bfloat162float(wb);
            }
            #pragma unroll
            for (int o = 16; o >= 1; o >>= 1) sw += __shfl_xor_sync(0xffffffffu, sw, o);
            if (lane == 0) atomicAdd(&sm->u.S[p], sw);

            // mixture softmax via lane shuffles (lanes 0..7 of even warps)
            if (d < MC){
                float sacc = 0.f;
                #pragma unroll 4
                for (int k = 0; k < Dd; k++){
                    float df = x[i*Dd + k] - means[d*Dd + k];
                    sacc += df*df;
                }
                float cm = -0.5f*sacc;
                float mx = cm;
                #pragma unroll
                for (int o = 4; o >= 1; o >>= 1) mx = fmaxf(mx, __shfl_xor_sync(0xffu, mx, o));
                float e = expf(cm - mx);
                float se = e;
                #pragma unroll
                for (int o = 4; o >= 1; o >>= 1) se += __shfl_xor_sync(0xffu, se, o);
                sm->u.wm[p][d] = e/se;
            }
            __syncthreads();

            // T = w[4x512] @ X[512x64] on tensor cores (8 warps, one n8-block each)
            {
                int w8 = tid >> 5;
                int g2 = lane >> 2, t2 = lane & 3;
                float accA[4] = {}, accB[4] = {};
                const __nv_bfloat16* Aw = sm->u.Aw;
                const __nv_bfloat16* Xt = sm->u.Xt + (size_t)(w8*8 + g2)*SX;
                #pragma unroll 8
                for (int kk = 0; kk < 32; kk++){
                    int kb = kk*16 + 2*t2;
                    unsigned a0 = *(const unsigned*)&Aw[g2*SX + kb];
                    unsigned a1 = *(const unsigned*)&Aw[(g2+8)*SX + kb];
                    unsigned a2 = *(const unsigned*)&Aw[g2*SX + kb + 8];
                    unsigned a3 = *(const unsigned*)&Aw[(g2+8)*SX + kb + 8];
                    unsigned b0 = *(const unsigned*)&Xt[kb];
                    unsigned b1 = *(const unsigned*)&Xt[kb + 8];
                    mma_bf16((kk & 1) ? accB : accA, a0, a1, a2, a3, b0, b1);
                }
                if (g2 < 4){
                    sm->u.T[g2*64 + w8*8 + 2*t2]     = accA[0] + accB[0];
                    sm->u.T[g2*64 + w8*8 + 2*t2 + 1] = accA[1] + accB[1];
                }
            }
            __syncthreads();

            // final update
            float dt = eps[0];
            float t = g_betas[s];
            float s2dt = sqrtf(2.f*dt);
            float xi_d = x[i*Dd + d];
            float Sp = sm->u.S[p];
            float Tv = sm->u.T[p*64 + d];
            float r = xi_d*Sp - Tv;
            float wbar = 0.f;
            #pragma unroll
            for (int m = 0; m < MC; m++) wbar += sm->u.wm[p][m]*means[m*Dd + d];
            float sc = out_b[d];
            #pragma unroll
            for (int nt = 0; nt < 16; nt++)
                sc += g_osp[((size_t)nt*Bp + i)*Dd + d];
            float drift = t*wbar - xi_d - sc;
            float nv = noises[((size_t)s*Bp + i)*Dd + d];
            xn[i*Dd + d] = xi_d + dt*drift + s2dt*nv + 0.1f*dt*inv_ht*r;
            // zero the OTHER histogram (used next step)
            for (int idx = gtid; idx < NBINS; idx += NT) g_hist[par^1][idx] = 0;
        }
        GB();
    }
}

extern "C" void kernel_launch(void* const* d_in, const int* in_sizes, int n_in,
                              void* d_out, int out_size){
    const float* particles = (const float*)d_in[0];
    const float* noises    = (const float*)d_in[1];
    const float* grid_t    = (const float*)d_in[2];
    const float* eps       = (const float*)d_in[3];
    const float* means     = (const float*)d_in[4];
    const float* phase     = (const float*)d_in[5];
    const float* in_W      = (const float*)d_in[6];
    const float* in_b      = (const float*)d_in[7];
    const float* t_W1      = (const float*)d_in[8];
    const float* t_b1      = (const float*)d_in[9];
    const float* t_W2      = (const float*)d_in[10];
    const float* t_b2      = (const float*)d_in[11];
    const float* h_W       = (const float*)d_in[12];
    const float* h_b       = (const float*)d_in[13];
    const float* out_W     = (const float*)d_in[14];
    const float* out_b     = (const float*)d_in[15];
    float* out = (float*)d_out;

    static int smem_set = -1;
    int smem_bytes = (int)sizeof(Smem);
    if (smem_set < 0){
        cudaFuncSetAttribute(cmcd_fused, cudaFuncAttributeMaxDynamicSharedMemorySize, smem_bytes);
        smem_set = 1;
    }

    cmcd_fused<<<GRID, TPB, smem_bytes>>>(particles, noises, grid_t, eps, means, phase,
                                          in_W, in_b, t_W1, t_b1, t_W2, t_b2,
                                          h_W, h_b, out_W, out_b, out);
}

// round 14
// speedup vs baseline: 2.5684x; 1.1459x over previous
#include <cuda_runtime.h>
#include <cuda_bf16.h>
#include <math.h>

#define GRID 128
#define TPB  256
#define Bp   512
#define Dd   64
#define Cc   512
#define NBs  8
#define MC   8
#define NBINS 32768
#define BIN_SC ((float)NBINS/64.0f)
#define BPAD 16

__device__ __nv_bfloat16 g_hA[Bp*Cc];
__device__ __nv_bfloat16 g_hB[Bp*Cc];
__device__ float g_osp[16*Bp*Dd];     // out-layer partials per n-tile
__device__ float g_d2[Bp*Bp];
__device__ float g_temb[NBs*2*Cc];
__device__ float g_tg1[NBs*Cc];
__device__ float g_bias1[NBs*Cc];
__device__ float g_betas[NBs+1];
__device__ __align__(16) int g_hist[2][NBINS];
__device__ unsigned long long g_flags[GRID*BPAD];
// weights transposed to [n][k] and converted to bf16 at setup
__device__ __nv_bfloat16 g_WinT[Cc*Dd];      // [n=Cc][k=Dd]
__device__ __nv_bfloat16 g_WhT[3*Cc*Cc];     // [l][n][k]
__device__ __nv_bfloat16 g_WoutT[Dd*Cc];     // [d][k]

#define SA 40    // smem half-stride (conflict-free frag loads)
#define SX 520   // P6 X/A stride

struct SmG {
    __nv_bfloat16 A[2][3][64*SA];   // [gid][stage]
    __nv_bfloat16 W[2][3][32*SA];
    float redf[64*33];
    __nv_bfloat16 redh[64*SA];
};
struct SmP { float Xi[32*64]; float Xj[64*64]; };
struct SmU {
    __nv_bfloat16 Xt[64*SX];
    __nv_bfloat16 Aw[16*SX];
    float T[4*64];
    float S[4];
    float wm[4][MC];
};
struct SmM { int cnt[8]; int woff[8]; float v[2]; };
union Smem { SmG g; SmP p; SmU u; SmM m; };

__device__ __forceinline__ float gelu_t(float x){
    float x3 = x*x*x;
    return 0.5f*x*(1.0f+tanhf(0.7978845608028654f*(x+0.044715f*x3)));
}

__device__ __forceinline__ unsigned bf2(float lo, float hi){
    unsigned r;
    asm("cvt.rn.bf16x2.f32 %0, %1, %2;" : "=r"(r) : "f"(hi), "f"(lo));
    return r;
}

__device__ __forceinline__ void mma_bf16(float* acc,
    unsigned a0, unsigned a1, unsigned a2, unsigned a3,
    unsigned b0, unsigned b1)
{
    asm volatile(
        "mma.sync.aligned.m16n8k16.row.col.f32.bf16.bf16.f32 "
        "{%0,%1,%2,%3}, {%4,%5,%6,%7}, {%8,%9}, {%0,%1,%2,%3};"
        : "+f"(acc[0]), "+f"(acc[1]), "+f"(acc[2]), "+f"(acc[3])
        : "r"(a0), "r"(a1), "r"(a2), "r"(a3), "r"(b0), "r"(b1));
}

__device__ __forceinline__ void cpa16(void* s, const void* g){
    unsigned sa = (unsigned)__cvta_generic_to_shared(s);
    asm volatile("cp.async.cg.shared.global [%0], [%1], 16;" :: "r"(sa), "l"(g));
}
#define CPA_COMMIT() asm volatile("cp.async.commit_group;" ::: "memory")

// all-to-all flag barrier: single L2 hop, no relay, no nanosleep.
__device__ __forceinline__ void gridbar2(int blk, int tid, unsigned long long target){
    __threadfence();
    __syncthreads();
    if (tid == 0)
        *((volatile unsigned long long*)&g_flags[blk*BPAD]) = target;
    if (tid < GRID){
        volatile unsigned long long* f = &g_flags[tid*BPAD];
        while (*f < target) { }
    }
    __syncthreads();
    __threadfence();
}

#define GB() do { ecnt++; gridbar2(blk, tid, ebase + ecnt); } while(0)

// one 64x32 output tile of C = act(A@W + bias) via bf16 tensor cores.
// 256 threads, 2-way K-split. WT is [n][k] bf16. C stored bf16.
// K=512 path: cp.async 3-stage ring. K=64 path (convA): register staging.
__device__ __forceinline__ void gemm_bf16(
    const void* Aptr, int Astr, int convA,
    const __nv_bfloat16* __restrict__ WT, int Wstr,
    int m0, int n0, int klen,
    const float* __restrict__ bias, int act,
    int fold, float* __restrict__ fold_out,
    __nv_bfloat16* __restrict__ C, int Cstr, Smem* sm)
{
    int tid  = threadIdx.x;
    int gid  = tid >> 7;
    int tg   = tid & 127;
    int warp = tg >> 5, lane = tid & 31;
    int g = lane >> 2, t = lane & 3;

    int arow = tg >> 1, kseg = (tg & 1)*16;   // A: 16 halves per thread
    int wn   = tg >> 2, kofs = (tg & 3)*8;    // W: 8 halves per thread

    int khalf = klen >> 1;
    int kb0   = gid*khalf;
    int NC    = khalf >> 5;

    float acc[4][4] = {};

    if (NC == 1){
        // single chunk (P1: fp32 x converted to bf16)
        const float* Af = (const float*)Aptr;
        const float* ap = &Af[(size_t)(m0+arow)*Astr + kb0 + kseg];
        float4 f0 = *(const float4*)ap,     f1 = *(const float4*)(ap+4);
        float4 f2 = *(const float4*)(ap+8), f3 = *(const float4*)(ap+12);
        uint4 ua, ub;
        ua.x = bf2(f0.x,f0.y); ua.y = bf2(f0.z,f0.w);
        ua.z = bf2(f1.x,f1.y); ua.w = bf2(f1.z,f1.w);
        ub.x = bf2(f2.x,f2.y); ub.y = bf2(f2.z,f2.w);
        ub.z = bf2(f3.x,f3.y); ub.w = bf2(f3.z,f3.w);
        uint4 uw = *(const uint4*)&WT[(size_t)(n0+wn)*Wstr + kb0 + kofs];
        __nv_bfloat16* As = sm->g.A[gid][0];
        __nv_bfloat16* Ws = sm->g.W[gid][0];
        *(uint4*)&As[arow*SA + kseg]     = ua;
        *(uint4*)&As[arow*SA + kseg + 8] = ub;
        *(uint4*)&Ws[wn*SA + kofs]       = uw;
        __syncthreads();
        #pragma unroll
        for (int kk = 0; kk < 2; kk++){
            int ab = (16*warp + g)*SA + kk*16 + 2*t;
            unsigned a0 = *(const unsigned*)&As[ab];
            unsigned a1 = *(const unsigned*)&As[ab + 8*SA];
            unsigned a2 = *(const unsigned*)&As[ab + 8];
            unsigned a3 = *(const unsigned*)&As[ab + 8*SA + 8];
            #pragma unroll
            for (int c4 = 0; c4 < 4; c4++){
                int bb = (c4*8 + g)*SA + kk*16 + 2*t;
                unsigned b0 = *(const unsigned*)&Ws[bb];
                unsigned b1 = *(const unsigned*)&Ws[bb + 8];
                mma_bf16(acc[c4], a0, a1, a2, a3, b0, b1);
            }
        }
    } else {
        const __nv_bfloat16* Ah = (const __nv_bfloat16*)Aptr;
        // stage chunk via cp.async (3 per thread: 2xA, 1xW)
        #define STAGE(chunk, st) do {                                            \
            int kb_ = kb0 + (chunk)*32;                                          \
            __nv_bfloat16* As_ = sm->g.A[gid][st];                               \
            __nv_bfloat16* Ws_ = sm->g.W[gid][st];                               \
            const __nv_bfloat16* ap_ = &Ah[(size_t)(m0+arow)*Astr + kb_ + kseg]; \
            cpa16(&As_[arow*SA + kseg], ap_);                                    \
            cpa16(&As_[arow*SA + kseg + 8], ap_ + 8);                            \
            cpa16(&Ws_[wn*SA + kofs], &WT[(size_t)(n0+wn)*Wstr + kb_ + kofs]);   \
            CPA_COMMIT();                                                        \
        } while(0)

        STAGE(0, 0);
        STAGE(1, 1);
        for (int c = 0; c < NC; c++){
            if (c+1 < NC) asm volatile("cp.async.wait_group 1;" ::: "memory");
            else          asm volatile("cp.async.wait_group 0;" ::: "memory");
            __syncthreads();
            if (c+2 < NC) STAGE(c+2, (c+2)%3);
            const __nv_bfloat16* As = sm->g.A[gid][c%3];
            const __nv_bfloat16* Ws = sm->g.W[gid][c%3];
            #pragma unroll
            for (int kk = 0; kk < 2; kk++){
                int ab = (16*warp + g)*SA + kk*16 + 2*t;
                unsigned a0 = *(const unsigned*)&As[ab];
                unsigned a1 = *(const unsigned*)&As[ab + 8*SA];
                unsigned a2 = *(const unsigned*)&As[ab + 8];
                unsigned a3 = *(const unsigned*)&As[ab + 8*SA + 8];
                #pragma unroll
                for (int c4 = 0; c4 < 4; c4++){
                    int bb = (c4*8 + g)*SA + kk*16 + 2*t;
                    unsigned b0 = *(const unsigned*)&Ws[bb];
                    unsigned b1 = *(const unsigned*)&Ws[bb + 8];
                    mma_bf16(acc[c4], a0, a1, a2, a3, b0, b1);
                }
            }
        }
        #undef STAGE
    }

    __syncthreads();
    int r0 = 16*warp + g;
    if (gid == 1){
        #pragma unroll
        for (int c4 = 0; c4 < 4; c4++){
            int col = c4*8 + 2*t;
            sm->g.redf[r0*33 + col]       = acc[c4][0];
            sm->g.redf[r0*33 + col + 1]   = acc[c4][1];
            sm->g.redf[(r0+8)*33 + col]   = acc[c4][2];
            sm->g.redf[(r0+8)*33 + col+1] = acc[c4][3];
        }
    }
    __syncthreads();
    if (gid == 0){
        #pragma unroll
        for (int c4 = 0; c4 < 4; c4++){
            int col = c4*8 + 2*t;
            float v00 = acc[c4][0] + sm->g.redf[r0*33 + col];
            float v01 = acc[c4][1] + sm->g.redf[r0*33 + col + 1];
            float v10 = acc[c4][2] + sm->g.redf[(r0+8)*33 + col];
            float v11 = acc[c4][3] + sm->g.redf[(r0+8)*33 + col+1];
            int n = n0 + col;
            if (bias){ v00 += bias[n]; v01 += bias[n+1]; v10 += bias[n]; v11 += bias[n+1]; }
            if (act){ v00 = gelu_t(v00); v01 = gelu_t(v01); v10 = gelu_t(v10); v11 = gelu_t(v11); }
            unsigned pv0 = bf2(v00, v01);
            unsigned pv1 = bf2(v10, v11);
            *(unsigned*)&C[(size_t)(m0+r0)*Cstr + n]   = pv0;
            *(unsigned*)&C[(size_t)(m0+r0+8)*Cstr + n] = pv1;
            if (fold){
                *(unsigned*)&sm->g.redh[r0*SA + col]     = pv0;
                *(unsigned*)&sm->g.redh[(r0+8)*SA + col] = pv1;
            }
        }
    }
    __syncthreads();

    if (fold){
        int w8 = tid >> 5;
        int wm = w8 & 3, wn2 = w8 >> 2;
        float acc2[4][4] = {};
        const __nv_bfloat16* R = sm->g.redh;
        #pragma unroll
        for (int kk = 0; kk < 2; kk++){
            int ab = (16*wm + g)*SA + kk*16 + 2*t;
            unsigned a0 = *(const unsigned*)&R[ab];
            unsigned a1 = *(const unsigned*)&R[ab + 8*SA];
            unsigned a2 = *(const unsigned*)&R[ab + 8];
            unsigned a3 = *(const unsigned*)&R[ab + 8*SA + 8];
            #pragma unroll
            for (int c4 = 0; c4 < 4; c4++){
                const __nv_bfloat16* wp =
                    &g_WoutT[(size_t)(32*wn2 + c4*8 + g)*Cc + n0 + kk*16 + 2*t];
                unsigned b0 = *(const unsigned*)wp;
                unsigned b1 = *(const unsigned*)(wp + 8);
                mma_bf16(acc2[c4], a0, a1, a2, a3, b0, b1);
            }
        }
        #pragma unroll
        for (int c4 = 0; c4 < 4; c4++){
            int row = m0 + 16*wm + g;
            int dcol = 32*wn2 + c4*8 + 2*t;
            fold_out[(size_t)row*Dd + dcol]       = acc2[c4][0];
            fold_out[(size_t)row*Dd + dcol + 1]   = acc2[c4][1];
            fold_out[(size_t)(row+8)*Dd + dcol]   = acc2[c4][2];
            fold_out[(size_t)(row+8)*Dd + dcol+1] = acc2[c4][3];
        }
        __syncthreads();
    }
}

// 32x64 tile of pairwise squared distances + histogram (256 threads)
__device__ __forceinline__ void pairwise_tile(const float* __restrict__ x, int i0, int j0,
                                              int* __restrict__ hist, Smem* sm){
    int tid = threadIdx.x;
    #pragma unroll
    for (int q = 0; q < 2; q++){
        int idx = tid + 256*q;
        int r = idx>>4, c4 = (idx&15)*4;
        if (r < 32){
            float4 v = *(const float4*)&x[(i0+r)*Dd + c4];
            sm->p.Xi[(c4+0)*32+r]=v.x; sm->p.Xi[(c4+1)*32+r]=v.y;
            sm->p.Xi[(c4+2)*32+r]=v.z; sm->p.Xi[(c4+3)*32+r]=v.w;
        }
    }
    #pragma unroll
    for (int q = 0; q < 4; q++){
        int idx = tid + 256*q;
        int row = idx>>4, c4 = (idx&15)*4;
        float4 v = *(const float4*)&x[(j0+row)*Dd + c4];
        sm->p.Xj[(c4+0)*64+row]=v.x; sm->p.Xj[(c4+1)*64+row]=v.y;
        sm->p.Xj[(c4+2)*64+row]=v.z; sm->p.Xj[(c4+3)*64+row]=v.w;
    }
    __syncthreads();
    int ty = tid>>4, tx = tid&15;
    float acc[2][4] = {};
    #pragma unroll
    for (int k = 0; k < 64; k++){
        float a0 = sm->p.Xi[k*32 + ty*2];
        float a1 = sm->p.Xi[k*32 + ty*2 + 1];
        float4 b = *(const float4*)&sm->p.Xj[k*64 + tx*4];
        float d;
        d=a0-b.x; acc[0][0]+=d*d;  d=a0-b.y; acc[0][1]+=d*d;
        d=a0-b.z; acc[0][2]+=d*d;  d=a0-b.w; acc[0][3]+=d*d;
        d=a1-b.x; acc[1][0]+=d*d;  d=a1-b.y; acc[1][1]+=d*d;
        d=a1-b.z; acc[1][2]+=d*d;  d=a1-b.w; acc[1][3]+=d*d;
    }
    #pragma unroll
    for (int i = 0; i < 2; i++){
        int gi = i0 + ty*2 + i;
        #pragma unroll
        for (int j = 0; j < 4; j++){
            int gj = j0 + tx*4 + j;
            float d2 = acc[i][j];
            g_d2[gi*Bp + gj] = d2;
            float dist = sqrtf(d2 > 0.f ? d2 : 1e-12f);
            int bin = (int)(dist*BIN_SC);
            if (bin > NBINS-1) bin = NBINS-1;
            atomicAdd(&hist[bin], 1);
        }
    }
    __syncthreads();
}

// exact median via warp-shuffle scan + warp-cooperative rank walk
__device__ __forceinline__ float median_local(const int* __restrict__ hist, Smem* sm){
    int tid = threadIdx.x, lane = tid & 31, warp = tid >> 5;
    const int per = NBINS/TPB;   // 128
    int ssum = 0;
    {
        const int4* h4 = (const int4*)(hist + tid*per);
        #pragma unroll 8
        for (int b = 0; b < per/4; b++){ int4 v = h4[b]; ssum += v.x+v.y+v.z+v.w; }
    }
    int incl = ssum;
    #pragma unroll
    for (int o = 1; o < 32; o <<= 1){
        int n = __shfl_up_sync(0xffffffffu, incl, o);
        if (lane >= o) incl += n;
    }
    if (lane == 31) sm->m.cnt[warp] = incl;
    __syncthreads();
    if (warp == 0 && lane < 8){
        int v = sm->m.cnt[lane];
        int sacc = v;
        #pragma unroll
        for (int o = 1; o < 8; o <<= 1){
            int n = __shfl_up_sync(0xffu, sacc, o);
            if (lane >= o) sacc += n;
        }
        sm->m.woff[lane] = sacc - v;
    }
    __syncthreads();
    int cur  = sm->m.woff[warp] + incl;
    int prev = cur - ssum;
    const int k1 = Bp*Bp/2, k2 = Bp*Bp/2 + 1;
    #pragma unroll
    for (int q = 0; q < 2; q++){
        int kq = (q == 0) ? k1 : k2;
        unsigned msk = __ballot_sync(0xffffffffu, prev < kq && kq <= cur);
        if (msk){
            int src   = __ffs(msk) - 1;
            int pbase = __shfl_sync(0xffffffffu, prev, src);
            int cbase = (__shfl_sync(0xffffffffu, tid, src))*per;
            int4 v = *(const int4*)(hist + cbase + lane*4);
            int sl = v.x+v.y+v.z+v.w;
            int i2 = sl;
            #pragma unroll
            for (int o = 1; o < 32; o <<= 1){
                int n = __shfl_up_sync(0xffffffffu, i2, o);
                if (lane >= o) i2 += n;
            }
            int cumL = pbase + i2, prevL = cumL - sl;
            if (prevL < kq && kq <= cumL){
                int b = cbase + lane*4, c = prevL, bb;
                c += v.x; if (c >= kq) bb = b;
                else { c += v.y; if (c >= kq) bb = b+1;
                       else { c += v.z; if (c >= kq) bb = b+2; else bb = b+3; } }
                sm->m.v[q] = ((float)bb + 0.5f)/BIN_SC;
            }
        }
    }
    __syncthreads();
    float med = 0.5f*(sm->m.v[0] + sm->m.v[1]);
    float ht = med*med / logf((float)Bp);
    __syncthreads();
    return ht;
}

__global__ void __launch_bounds__(TPB, 1)
cmcd_fused(const float* __restrict__ particles, const float* __restrict__ noises,
           const float* __restrict__ grid_t, const float* __restrict__ eps,
           const float* __restrict__ means, const float* __restrict__ phase,
           const float* __restrict__ in_W, const float* __restrict__ in_b,
           const float* __restrict__ t_W1, const float* __restrict__ t_b1,
           const float* __restrict__ t_W2, const float* __restrict__ t_b2,
           const float* __restrict__ h_W, const float* __restrict__ h_b,
           const float* __restrict__ out_W, const float* __restrict__ out_b,
           float* __restrict__ out)
{
    extern __shared__ unsigned char smem_raw[];
    Smem* sm = reinterpret_cast<Smem*>(smem_raw);
    int blk = blockIdx.x, tid = threadIdx.x;
    int gtid = blk*TPB + tid;
    const int NT = GRID*TPB;

    unsigned long long ebase = *((volatile unsigned long long*)&g_flags[blk*BPAD]);
    unsigned long long ecnt = 0;

    // ── S0: copy slice 0, zero hists, temb, betas, transposed bf16 weights ──
    for (int idx = gtid; idx < Bp*Dd; idx += NT) out[idx] = particles[idx];
    for (int idx = gtid; idx < 2*NBINS; idx += NT) g_hist[0][idx] = 0;
    for (int idx = gtid; idx < Cc*Dd; idx += NT){
        int n = idx & 511, k = idx >> 9;
        g_WinT[n*Dd + k] = __float2bfloat16(in_W[k*Cc + n]);
    }
    for (int idx = gtid; idx < 3*Cc*Cc; idx += NT){
        int l = idx >> 18, r = idx & 262143;
        int n = r & 511, k = r >> 9;
        g_WhT[l*262144 + n*Cc + k] = __float2bfloat16(h_W[l*262144 + k*Cc + n]);
    }
    for (int idx = gtid; idx < Cc*Dd; idx += NT){
        int d = idx & 63, k = idx >> 6;
        g_WoutT[d*Cc + k] = __float2bfloat16(out_W[k*Dd + d]);
    }
    for (int idx = gtid; idx < NBs*2*Cc; idx += NT){
        int s = idx >> 10, c = idx & 1023;
        float t = (float)s;
        int cc = (c < Cc) ? c : c - Cc;
        float coeff = 0.1f + (float)cc*(99.9f/511.0f);
        float e = coeff*t + phase[cc];
        g_temb[idx] = (c < Cc) ? sinf(e) : cosf(e);
    }
    if (gtid == 0){
        float cum = 0.f;
        g_betas[0] = 0.f;
        for (int j = 0; j < NBs; j++){
            float sg = 1.f/(1.f+expf(-grid_t[j]));
            cum += sg;
            g_betas[j+1] = cum;
        }
        float inv = 1.f/cum;
        for (int j = 1; j <= NBs; j++) g_betas[j] *= inv;
    }
    GB();

    // ── S1: t-MLP layer 1 (8-way K-split + shuffle reduce) ──
    {
        int oidx = gtid >> 3;
        int sl   = gtid & 7;
        int s = oidx >> 9, c = oidx & 511;
        float acc = 0.f;
        const float* tb = g_temb + s*2*Cc;
        int kb = sl*128;
        #pragma unroll 4
        for (int k = kb; k < kb+128; k++) acc += tb[k]*t_W1[k*Cc + c];
        #pragma unroll
        for (int o = 1; o < 8; o <<= 1) acc += __shfl_xor_sync(0xffffffffu, acc, o);
        if (sl == 0) g_tg1[oidx] = gelu_t(acc + t_b1[c]);
    }
    GB();

    // ── S2: t-MLP layer 2 + in_b → fused input bias ──
    {
        int oidx = gtid >> 3;
        int sl   = gtid & 7;
        int s = oidx >> 9, c = oidx & 511;
        float acc = 0.f;
        const float* gb = g_tg1 + s*Cc;
        int kb = sl*64;
        #pragma unroll 4
        for (int k = kb; k < kb+64; k++) acc += gb[k]*t_W2[k*Cc + c];
        #pragma unroll
        for (int o = 1; o < 8; o <<= 1) acc += __shfl_xor_sync(0xffffffffu, acc, o);
        if (sl == 0) g_bias1[oidx] = acc + t_b2[c] + in_b[c];
    }
    GB();

    int m0 = (blk >> 4) * 64;
    int n0 = (blk & 15) * 32;
    float* fold_out = g_osp + (size_t)(blk & 15)*Bp*Dd;

    for (int s = 0; s < NBs; s++){
        const float* x = out + (size_t)s*Bp*Dd;
        float* xn      = out + (size_t)(s+1)*Bp*Dd;
        int par = s & 1;

        // ── P1: input layer (K=64, fp32 x converted) + pairwise d2/hist ──
        gemm_bf16(x, Dd, 1, g_WinT, Dd, m0, n0, Dd, g_bias1 + s*Cc, 1, 0, nullptr, g_hA, Cc, sm);
        pairwise_tile(x, (blk>>3)*32, (blk&7)*64, g_hist[par], sm);
        GB();

        // ── P2-P4: hidden layers (P4 folds out-layer partials) ──
        gemm_bf16(g_hA, Cc, 0, g_WhT + 0*Cc*Cc, Cc, m0, n0, Cc, h_b + 0*Cc, 1, 0, nullptr, g_hB, Cc, sm);
        GB();
        gemm_bf16(g_hB, Cc, 0, g_WhT + 1*Cc*Cc, Cc, m0, n0, Cc, h_b + 1*Cc, 1, 0, nullptr, g_hA, Cc, sm);
        GB();
        gemm_bf16(g_hA, Cc, 0, g_WhT + 2*Cc*Cc, Cc, m0, n0, Cc, h_b + 2*Cc, 1, 1, fold_out, g_hB, Cc, sm);
        GB();

        // ── P6: median + tensorized repulsion + update ──
        {
            float ht = median_local(g_hist[par], sm);
            float inv_ht = 1.f/ht;
            int lane = tid & 31;
            int p = tid >> 6;
            int d = tid & 63;
            int i = blk*4 + p;

            for (int it = tid; it < 8192; it += TPB){
                int j = it >> 4, d4 = (it & 15)*4;
                float4 v = *(const float4*)&x[j*Dd + d4];
                sm->u.Xt[(d4+0)*SX + j] = __float2bfloat16(v.x);
                sm->u.Xt[(d4+1)*SX + j] = __float2bfloat16(v.y);
                sm->u.Xt[(d4+2)*SX + j] = __float2bfloat16(v.z);
                sm->u.Xt[(d4+3)*SX + j] = __float2bfloat16(v.w);
            }
            for (int it = tid; it < 12*SX/2; it += TPB)
                ((unsigned*)(sm->u.Aw + 4*SX))[it] = 0;
            if (tid < 4) sm->u.S[tid] = 0.f;
            __syncthreads();

            float sw = 0.f;
            #pragma unroll
            for (int q = 0; q < 8; q++){
                int j = d + q*64;
                float wv = expf(-g_d2[i*Bp + j]*inv_ht);
                __nv_bfloat16 wb = __float2bfloat16(wv);
                sm->u.Aw[p*SX + j] = wb;
                sw += __bfloat162float(wb);
            }
            #pragma unroll
            for (int o = 16; o >= 1; o >>= 1) sw += __shfl_xor_sync(0xffffffffu, sw, o);
            if (lane == 0) atomicAdd(&sm->u.S[p], sw);

            if (d < MC){
                float sacc = 0.f;
                #pragma unroll 4
                for (int k = 0; k < Dd; k++){
                    float df = x[i*Dd + k] - means[d*Dd + k];
                    sacc += df*df;
                }
                float cm = -0.5f*sacc;
                float mx = cm;
                #pragma unroll
                for (int o = 4; o >= 1; o >>= 1) mx = fmaxf(mx, __shfl_xor_sync(0xffu, mx, o));
                float e = expf(cm - mx);
                float se = e;
                #pragma unroll
                for (int o = 4; o >= 1; o >>= 1) se += __shfl_xor_sync(0xffu, se, o);
                sm->u.wm[p][d] = e/se;
            }
            __syncthreads();

            {
                int w8 = tid >> 5;
                int g2 = lane >> 2, t2 = lane & 3;
                float accA[4] = {}, accB[4] = {};
                const __nv_bfloat16* Aw = sm->u.Aw;
                const __nv_bfloat16* Xt = sm->u.Xt + (size_t)(w8*8 + g2)*SX;
                #pragma unroll 8
                for (int kk = 0; kk < 32; kk++){
                    int kb = kk*16 + 2*t2;
                    unsigned a0 = *(const unsigned*)&Aw[g2*SX + kb];
                    unsigned a1 = *(const unsigned*)&Aw[(g2+8)*SX + kb];
                    unsigned a2 = *(const unsigned*)&Aw[g2*SX + kb + 8];
                    unsigned a3 = *(const unsigned*)&Aw[(g2+8)*SX + kb + 8];
                    unsigned b0 = *(const unsigned*)&Xt[kb];
                    unsigned b1 = *(const unsigned*)&Xt[kb + 8];
                    mma_bf16((kk & 1) ? accB : accA, a0, a1, a2, a3, b0, b1);
                }
                if (g2 < 4){
                    sm->u.T[g2*64 + w8*8 + 2*t2]     = accA[0] + accB[0];
                    sm->u.T[g2*64 + w8*8 + 2*t2 + 1] = accA[1] + accB[1];
                }
            }
            __syncthreads();

            float dt = eps[0];
            float t = g_betas[s];
            float s2dt = sqrtf(2.f*dt);
            float xi_d = x[i*Dd + d];
            float Sp = sm->u.S[p];
            float Tv = sm->u.T[p*64 + d];
            float r = xi_d*Sp - Tv;
            float wbar = 0.f;
            #pragma unroll
            for (int m = 0; m < MC; m++) wbar += sm->u.wm[p][m]*means[m*Dd + d];
            float sc = out_b[d];
            #pragma unroll
            for (int nt = 0; nt < 16; nt++)
                sc += g_osp[((size_t)nt*Bp + i)*Dd + d];
            float drift = t*wbar - xi_d - sc;
            float nv = noises[((size_t)s*Bp + i)*Dd + d];
            xn[i*Dd + d] = xi_d + dt*drift + s2dt*nv + 0.1f*dt*inv_ht*r;
            for (int idx = gtid; idx < NBINS; idx += NT) g_hist[par^1][idx] = 0;
        }
        GB();
    }
}

extern "C" void kernel_launch(void* const* d_in, const int* in_sizes, int n_in,
                              void* d_out, int out_size){
    const float* particles = (const float*)d_in[0];
    const float* noises    = (const float*)d_in[1];
    const float* grid_t    = (const float*)d_in[2];
    const float* eps       = (const float*)d_in[3];
    const float* means     = (const float*)d_in[4];
    const float* phase     = (const float*)d_in[5];
    const float* in_W      = (const float*)d_in[6];
    const float* in_b      = (const float*)d_in[7];
    const float* t_W1      = (const float*)d_in[8];
    const float* t_b1      = (const float*)d_in[9];
    const float* t_W2      = (const float*)d_in[10];
    const float* t_b2      = (const float*)d_in[11];
    const float* h_W       = (const float*)d_in[12];
    const float* h_b       = (const float*)d_in[13];
    const float* out_W     = (const float*)d_in[14];
    const float* out_b     = (const float*)d_in[15];
    float* out = (float*)d_out;

    static int smem_set = -1;
    int smem_bytes = (int)sizeof(Smem);
    if (smem_set < 0){
        cudaFuncSetAttribute(cmcd_fused, cudaFuncAttributeMaxDynamicSharedMemorySize, smem_bytes);
        smem_set = 1;
    }

    cmcd_fused<<<GRID, TPB, smem_bytes>>>(particles, noises, grid_t, eps, means, phase,
                                          in_W, in_b, t_W1, t_b1, t_W2, t_b2,
                                          h_W, h_b, out_W, out_b, out);
}

// round 15
// speedup vs baseline: 2.6729x; 1.0407x over previous
#include <cuda_runtime.h>
#include <cuda_bf16.h>
#include <math.h>

#define GRID 128
#define TPB  256
#define Bp   512
#define Dd   64
#define Cc   512
#define NBs  8
#define MC   8
#define NBINS 32768
#define BIN_SC ((float)NBINS/64.0f)
#define BPAD 16

__device__ __nv_bfloat16 g_hA[Bp*Cc];
__device__ __nv_bfloat16 g_hB[Bp*Cc];
__device__ float g_osp[16*Bp*Dd];     // out-layer partials per n-tile
__device__ float g_d2[Bp*Bp];
__device__ float g_temb[NBs*2*Cc];
__device__ float g_tg1[NBs*Cc];
__device__ float g_bias1[NBs*Cc];
__device__ float g_betas[NBs+1];
__device__ __align__(16) int g_hist[2][NBINS];
__device__ unsigned long long g_flags[GRID*BPAD];
// weights transposed to [n][k] and converted to bf16 at setup
__device__ __nv_bfloat16 g_WinT[Cc*Dd];      // [n=Cc][k=Dd]
__device__ __nv_bfloat16 g_WhT[3*Cc*Cc];     // [l][n][k]
__device__ __nv_bfloat16 g_WoutT[Dd*Cc];     // [d][k]

#define SA 72    // smem half-stride for 64-half chunks (conflict-free frags)
#define SX 520   // P6 X/A stride

struct SmG {
    __nv_bfloat16 A[2][3][64*SA];   // [gid][stage]
    __nv_bfloat16 W[2][3][32*SA];
    float redf[64*33];
    __nv_bfloat16 redh[64*SA];
};
struct SmP { float Xi[32*64]; float Xj[64*64]; };
struct SmU {
    __nv_bfloat16 Xt[64*SX];
    __nv_bfloat16 Aw[16*SX];
    float T[4*64];
    float S[4];
    float wm[4][MC];
};
struct SmM { int cnt[8]; int woff[8]; float v[2]; };
union Smem { SmG g; SmP p; SmU u; SmM m; };

__device__ __forceinline__ float gelu_t(float x){
    float x3 = x*x*x;
    return 0.5f*x*(1.0f+tanhf(0.7978845608028654f*(x+0.044715f*x3)));
}

__device__ __forceinline__ unsigned bf2(float lo, float hi){
    unsigned r;
    asm("cvt.rn.bf16x2.f32 %0, %1, %2;" : "=r"(r) : "f"(hi), "f"(lo));
    return r;
}

__device__ __forceinline__ void mma_bf16(float* acc,
    unsigned a0, unsigned a1, unsigned a2, unsigned a3,
    unsigned b0, unsigned b1)
{
    asm volatile(
        "mma.sync.aligned.m16n8k16.row.col.f32.bf16.bf16.f32 "
        "{%0,%1,%2,%3}, {%4,%5,%6,%7}, {%8,%9}, {%0,%1,%2,%3};"
        : "+f"(acc[0]), "+f"(acc[1]), "+f"(acc[2]), "+f"(acc[3])
        : "r"(a0), "r"(a1), "r"(a2), "r"(a3), "r"(b0), "r"(b1));
}

__device__ __forceinline__ void cpa16(void* s, const void* g){
    unsigned sa = (unsigned)__cvta_generic_to_shared(s);
    asm volatile("cp.async.cg.shared.global [%0], [%1], 16;" :: "r"(sa), "l"(g));
}
#define CPA_COMMIT() asm volatile("cp.async.commit_group;" ::: "memory")

// L2-direct loads (bypass L1) for cross-phase re-read data
__device__ __forceinline__ float4 ldcg4(const float* p){
    float4 v;
    asm volatile("ld.global.cg.v4.f32 {%0,%1,%2,%3}, [%4];"
                 : "=f"(v.x),"=f"(v.y),"=f"(v.z),"=f"(v.w) : "l"(p));
    return v;
}
__device__ __forceinline__ float ldcg1(const float* p){
    float v;
    asm volatile("ld.global.cg.f32 %0, [%1];" : "=f"(v) : "l"(p));
    return v;
}
__device__ __forceinline__ int4 ldcg4i(const int* p){
    int4 v;
    asm volatile("ld.global.cg.v4.s32 {%0,%1,%2,%3}, [%4];"
                 : "=r"(v.x),"=r"(v.y),"=r"(v.z),"=r"(v.w) : "l"(p));
    return v;
}

// release/acquire flag barrier: NO threadfence -> no CCTL.IVALL L1 flush.
// bar.sync CTA edges compose with the gpu-scope release/acquire (PTX model).
__device__ __forceinline__ void gridbar2(int blk, int tid, unsigned long long target){
    __syncthreads();
    if (tid == 0)
        asm volatile("st.release.gpu.global.u64 [%0], %1;"
                     :: "l"(&g_flags[blk*BPAD]), "l"(target) : "memory");
    if (tid < GRID){
        unsigned long long v;
        do {
            asm volatile("ld.acquire.gpu.global.u64 %0, [%1];"
                         : "=l"(v) : "l"(&g_flags[tid*BPAD]) : "memory");
        } while (v < target);
    }
    __syncthreads();
}

#define GB() do { ecnt++; gridbar2(blk, tid, ebase + ecnt); } while(0)

// one 64x32 output tile of C = act(A@W + bias) via bf16 tensor cores.
// 256 threads, 2-way K-split. WT is [n][k] bf16. C stored bf16.
// K=512: cp.async 3-stage ring, 64-half chunks. K=64 (convA): register conv.
__device__ __forceinline__ void gemm_bf16(
    const void* Aptr, int Astr, int convA,
    const __nv_bfloat16* __restrict__ WT, int Wstr,
    int m0, int n0, int klen,
    const float* __restrict__ bias, int act,
    int fold, float* __restrict__ fold_out,
    __nv_bfloat16* __restrict__ C, int Cstr, Smem* sm)
{
    int tid  = threadIdx.x;
    int gid  = tid >> 7;
    int tg   = tid & 127;
    int warp = tg >> 5, lane = tid & 31;
    int g = lane >> 2, t = lane & 3;

    float acc[4][4] = {};

    if (convA){
        // single 32-half chunk per gid (P1: fp32 x converted to bf16)
        int kb0 = gid*32;
        int arow = tg >> 1, kseg = (tg & 1)*16;
        int wn   = tg >> 2, kofs = (tg & 3)*8;
        const float* Af = (const float*)Aptr;
        const float* ap = &Af[(size_t)(m0+arow)*Astr + kb0 + kseg];
        float4 f0 = ldcg4(ap),   f1 = ldcg4(ap+4);
        float4 f2 = ldcg4(ap+8), f3 = ldcg4(ap+12);
        uint4 ua, ub;
        ua.x = bf2(f0.x,f0.y); ua.y = bf2(f0.z,f0.w);
        ua.z = bf2(f1.x,f1.y); ua.w = bf2(f1.z,f1.w);
        ub.x = bf2(f2.x,f2.y); ub.y = bf2(f2.z,f2.w);
        ub.z = bf2(f3.x,f3.y); ub.w = bf2(f3.z,f3.w);
        uint4 uw = *(const uint4*)&WT[(size_t)(n0+wn)*Wstr + kb0 + kofs];
        __nv_bfloat16* As = sm->g.A[gid][0];
        __nv_bfloat16* Ws = sm->g.W[gid][0];
        *(uint4*)&As[arow*SA + kseg]     = ua;
        *(uint4*)&As[arow*SA + kseg + 8] = ub;
        *(uint4*)&Ws[wn*SA + kofs]       = uw;
        __syncthreads();
        #pragma unroll
        for (int kk = 0; kk < 2; kk++){
            int ab = (16*warp + g)*SA + kk*16 + 2*t;
            unsigned a0 = *(const unsigned*)&As[ab];
            unsigned a1 = *(const unsigned*)&As[ab + 8*SA];
            unsigned a2 = *(const unsigned*)&As[ab + 8];
            unsigned a3 = *(const unsigned*)&As[ab + 8*SA + 8];
            #pragma unroll
            for (int c4 = 0; c4 < 4; c4++){
                int bb = (c4*8 + g)*SA + kk*16 + 2*t;
                unsigned b0 = *(const unsigned*)&Ws[bb];
                unsigned b1 = *(const unsigned*)&Ws[bb + 8];
                mma_bf16(acc[c4], a0, a1, a2, a3, b0, b1);
            }
        }
    } else {
        // K=512: 4 chunks of 64 halves per gid, 3-stage cp.async ring
        const __nv_bfloat16* Ah = (const __nv_bfloat16*)Aptr;
        int kb0 = gid*256;
        #define STAGE64(chunk, st) do {                                           \
            int kb_ = kb0 + (chunk)*64;                                           \
            __nv_bfloat16* As_ = sm->g.A[gid][st];                                \
            __nv_bfloat16* Ws_ = sm->g.W[gid][st];                                \
            _Pragma("unroll")                                                     \
            for (int q = 0; q < 4; q++){                                          \
                int u = tg + q*128;                                               \
                cpa16(&As_[(u>>3)*SA + (u&7)*8],                                  \
                      &Ah[(size_t)(m0+(u>>3))*Astr + kb_ + (u&7)*8]);             \
            }                                                                     \
            _Pragma("unroll")                                                     \
            for (int q = 0; q < 2; q++){                                          \
                int u = tg + q*128;                                               \
                cpa16(&Ws_[(u>>3)*SA + (u&7)*8],                                  \
                      &WT[(size_t)(n0+(u>>3))*Wstr + kb_ + (u&7)*8]);             \
            }                                                                     \
            CPA_COMMIT();                                                         \
        } while(0)

        STAGE64(0, 0);
        STAGE64(1, 1);
        #pragma unroll
        for (int c = 0; c < 4; c++){
            if (c < 3) asm volatile("cp.async.wait_group 1;" ::: "memory");
            else       asm volatile("cp.async.wait_group 0;" ::: "memory");
            __syncthreads();
            if (c+2 < 4) STAGE64(c+2, (c+2)%3);
            const __nv_bfloat16* As = sm->g.A[gid][c%3];
            const __nv_bfloat16* Ws = sm->g.W[gid][c%3];
            #pragma unroll
            for (int kk = 0; kk < 4; kk++){
                int ab = (16*warp + g)*SA + kk*16 + 2*t;
                unsigned a0 = *(const unsigned*)&As[ab];
                unsigned a1 = *(const unsigned*)&As[ab + 8*SA];
                unsigned a2 = *(const unsigned*)&As[ab + 8];
                unsigned a3 = *(const unsigned*)&As[ab + 8*SA + 8];
                #pragma unroll
                for (int c4 = 0; c4 < 4; c4++){
                    int bb = (c4*8 + g)*SA + kk*16 + 2*t;
                    unsigned b0 = *(const unsigned*)&Ws[bb];
                    unsigned b1 = *(const unsigned*)&Ws[bb + 8];
                    mma_bf16(acc[c4], a0, a1, a2, a3, b0, b1);
                }
            }
        }
        #undef STAGE64
    }

    __syncthreads();
    int r0 = 16*warp + g;
    if (gid == 1){
        #pragma unroll
        for (int c4 = 0; c4 < 4; c4++){
            int col = c4*8 + 2*t;
            sm->g.redf[r0*33 + col]       = acc[c4][0];
            sm->g.redf[r0*33 + col + 1]   = acc[c4][1];
            sm->g.redf[(r0+8)*33 + col]   = acc[c4][2];
            sm->g.redf[(r0+8)*33 + col+1] = acc[c4][3];
        }
    }
    __syncthreads();
    if (gid == 0){
        #pragma unroll
        for (int c4 = 0; c4 < 4; c4++){
            int col = c4*8 + 2*t;
            float v00 = acc[c4][0] + sm->g.redf[r0*33 + col];
            float v01 = acc[c4][1] + sm->g.redf[r0*33 + col + 1];
            float v10 = acc[c4][2] + sm->g.redf[(r0+8)*33 + col];
            float v11 = acc[c4][3] + sm->g.redf[(r0+8)*33 + col+1];
            int n = n0 + col;
            if (bias){ v00 += bias[n]; v01 += bias[n+1]; v10 += bias[n]; v11 += bias[n+1]; }
            if (act){ v00 = gelu_t(v00); v01 = gelu_t(v01); v10 = gelu_t(v10); v11 = gelu_t(v11); }
            unsigned pv0 = bf2(v00, v01);
            unsigned pv1 = bf2(v10, v11);
            *(unsigned*)&C[(size_t)(m0+r0)*Cstr + n]   = pv0;
            *(unsigned*)&C[(size_t)(m0+r0+8)*Cstr + n] = pv1;
            if (fold){
                *(unsigned*)&sm->g.redh[r0*SA + col]     = pv0;
                *(unsigned*)&sm->g.redh[(r0+8)*SA + col] = pv1;
            }
        }
    }
    __syncthreads();

    if (fold){
        int w8 = tid >> 5;
        int wm = w8 & 3, wn2 = w8 >> 2;
        float acc2[4][4] = {};
        const __nv_bfloat16* R = sm->g.redh;
        #pragma unroll
        for (int kk = 0; kk < 2; kk++){
            int ab = (16*wm + g)*SA + kk*16 + 2*t;
            unsigned a0 = *(const unsigned*)&R[ab];
            unsigned a1 = *(const unsigned*)&R[ab + 8*SA];
            unsigned a2 = *(const unsigned*)&R[ab + 8];
            unsigned a3 = *(const unsigned*)&R[ab + 8*SA + 8];
            #pragma unroll
            for (int c4 = 0; c4 < 4; c4++){
                const __nv_bfloat16* wp =
                    &g_WoutT[(size_t)(32*wn2 + c4*8 + g)*Cc + n0 + kk*16 + 2*t];
                unsigned b0 = *(const unsigned*)wp;
                unsigned b1 = *(const unsigned*)(wp + 8);
                mma_bf16(acc2[c4], a0, a1, a2, a3, b0, b1);
            }
        }
        #pragma unroll
        for (int c4 = 0; c4 < 4; c4++){
            int row = m0 + 16*wm + g;
            int dcol = 32*wn2 + c4*8 + 2*t;
            fold_out[(size_t)row*Dd + dcol]       = acc2[c4][0];
            fold_out[(size_t)row*Dd + dcol + 1]   = acc2[c4][1];
            fold_out[(size_t)(row+8)*Dd + dcol]   = acc2[c4][2];
            fold_out[(size_t)(row+8)*Dd + dcol+1] = acc2[c4][3];
        }
        __syncthreads();
    }
}

// 32x64 tile of pairwise squared distances + histogram (256 threads)
__device__ __forceinline__ void pairwise_tile(const float* __restrict__ x, int i0, int j0,
                                              int* __restrict__ hist, Smem* sm){
    int tid = threadIdx.x;
    #pragma unroll
    for (int q = 0; q < 2; q++){
        int idx = tid + 256*q;
        int r = idx>>4, c4 = (idx&15)*4;
        if (r < 32){
            float4 v = ldcg4(&x[(i0+r)*Dd + c4]);
            sm->p.Xi[(c4+0)*32+r]=v.x; sm->p.Xi[(c4+1)*32+r]=v.y;
            sm->p.Xi[(c4+2)*32+r]=v.z; sm->p.Xi[(c4+3)*32+r]=v.w;
        }
    }
    #pragma unroll
    for (int q = 0; q < 4; q++){
        int idx = tid + 256*q;
        int row = idx>>4, c4 = (idx&15)*4;
        float4 v = ldcg4(&x[(j0+row)*Dd + c4]);
        sm->p.Xj[(c4+0)*64+row]=v.x; sm->p.Xj[(c4+1)*64+row]=v.y;
        sm->p.Xj[(c4+2)*64+row]=v.z; sm->p.Xj[(c4+3)*64+row]=v.w;
    }
    __syncthreads();
    int ty = tid>>4, tx = tid&15;
    float acc[2][4] = {};
    #pragma unroll
    for (int k = 0; k < 64; k++){
        float a0 = sm->p.Xi[k*32 + ty*2];
        float a1 = sm->p.Xi[k*32 + ty*2 + 1];
        float4 b = *(const float4*)&sm->p.Xj[k*64 + tx*4];
        float d;
        d=a0-b.x; acc[0][0]+=d*d;  d=a0-b.y; acc[0][1]+=d*d;
        d=a0-b.z; acc[0][2]+=d*d;  d=a0-b.w; acc[0][3]+=d*d;
        d=a1-b.x; acc[1][0]+=d*d;  d=a1-b.y; acc[1][1]+=d*d;
        d=a1-b.z; acc[1][2]+=d*d;  d=a1-b.w; acc[1][3]+=d*d;
    }
    #pragma unroll
    for (int i = 0; i < 2; i++){
        int gi = i0 + ty*2 + i;
        #pragma unroll
        for (int j = 0; j < 4; j++){
            int gj = j0 + tx*4 + j;
            float d2 = acc[i][j];
            g_d2[gi*Bp + gj] = d2;
            float dist = sqrtf(d2 > 0.f ? d2 : 1e-12f);
            int bin = (int)(dist*BIN_SC);
            if (bin > NBINS-1) bin = NBINS-1;
            atomicAdd(&hist[bin], 1);
        }
    }
    __syncthreads();
}

// exact median via warp-shuffle scan + warp-cooperative rank walk
__device__ __forceinline__ float median_local(const int* __restrict__ hist, Smem* sm){
    int tid = threadIdx.x, lane = tid & 31, warp = tid >> 5;
    const int per = NBINS/TPB;   // 128
    int ssum = 0;
    {
        const int* hp = hist + tid*per;
        #pragma unroll 8
        for (int b = 0; b < per/4; b++){
            int4 v = ldcg4i(hp + b*4);
            ssum += v.x+v.y+v.z+v.w;
        }
    }
    int incl = ssum;
    #pragma unroll
    for (int o = 1; o < 32; o <<= 1){
        int n = __shfl_up_sync(0xffffffffu, incl, o);
        if (lane >= o) incl += n;
    }
    if (lane == 31) sm->m.cnt[warp] = incl;
    __syncthreads();
    if (warp == 0 && lane < 8){
        int v = sm->m.cnt[lane];
        int sacc = v;
        #pragma unroll
        for (int o = 1; o < 8; o <<= 1){
            int n = __shfl_up_sync(0xffu, sacc, o);
            if (lane >= o) sacc += n;
        }
        sm->m.woff[lane] = sacc - v;
    }
    __syncthreads();
    int cur  = sm->m.woff[warp] + incl;
    int prev = cur - ssum;
    const int k1 = Bp*Bp/2, k2 = Bp*Bp/2 + 1;
    #pragma unroll
    for (int q = 0; q < 2; q++){
        int kq = (q == 0) ? k1 : k2;
        unsigned msk = __ballot_sync(0xffffffffu, prev < kq && kq <= cur);
        if (msk){
            int src   = __ffs(msk) - 1;
            int pbase = __shfl_sync(0xffffffffu, prev, src);
            int cbase = (__shfl_sync(0xffffffffu, tid, src))*per;
            int4 v = ldcg4i(hist + cbase + lane*4);
            int sl = v.x+v.y+v.z+v.w;
            int i2 = sl;
            #pragma unroll
            for (int o = 1; o < 32; o <<= 1){
                int n = __shfl_up_sync(0xffffffffu, i2, o);
                if (lane >= o) i2 += n;
            }
            int cumL = pbase + i2, prevL = cumL - sl;
            if (prevL < kq && kq <= cumL){
                int b = cbase + lane*4, c = prevL, bb;
                c += v.x; if (c >= kq) bb = b;
                else { c += v.y; if (c >= kq) bb = b+1;
                       else { c += v.z; if (c >= kq) bb = b+2; else bb = b+3; } }
                sm->m.v[q] = ((float)bb + 0.5f)/BIN_SC;
            }
        }
    }
    __syncthreads();
    float med = 0.5f*(sm->m.v[0] + sm->m.v[1]);
    float ht = med*med / logf((float)Bp);
    __syncthreads();
    return ht;
}

__global__ void __launch_bounds__(TPB, 1)
cmcd_fused(const float* __restrict__ particles, const float* __restrict__ noises,
           const float* __restrict__ grid_t, const float* __restrict__ eps,
           const float* __restrict__ means, const float* __restrict__ phase,
           const float* __restrict__ in_W, const float* __restrict__ in_b,
           const float* __restrict__ t_W1, const float* __restrict__ t_b1,
           const float* __restrict__ t_W2, const float* __restrict__ t_b2,
           const float* __restrict__ h_W, const float* __restrict__ h_b,
           const float* __restrict__ out_W, const float* __restrict__ out_b,
           float* __restrict__ out)
{
    extern __shared__ unsigned char smem_raw[];
    Smem* sm = reinterpret_cast<Smem*>(smem_raw);
    int blk = blockIdx.x, tid = threadIdx.x;
    int gtid = blk*TPB + tid;
    const int NT = GRID*TPB;

    unsigned long long ebase;
    asm volatile("ld.acquire.gpu.global.u64 %0, [%1];"
                 : "=l"(ebase) : "l"(&g_flags[blk*BPAD]));
    unsigned long long ecnt = 0;

    // ── S0: copy slice 0, zero hists, temb, betas, transposed bf16 weights ──
    for (int idx = gtid; idx < Bp*Dd; idx += NT) out[idx] = particles[idx];
    for (int idx = gtid; idx < 2*NBINS; idx += NT) g_hist[0][idx] = 0;
    for (int idx = gtid; idx < Cc*Dd; idx += NT){
        int n = idx & 511, k = idx >> 9;
        g_WinT[n*Dd + k] = __float2bfloat16(in_W[k*Cc + n]);
    }
    for (int idx = gtid; idx < 3*Cc*Cc; idx += NT){
        int l = idx >> 18, r = idx & 262143;
        int n = r & 511, k = r >> 9;
        g_WhT[l*262144 + n*Cc + k] = __float2bfloat16(h_W[l*262144 + k*Cc + n]);
    }
    for (int idx = gtid; idx < Cc*Dd; idx += NT){
        int d = idx & 63, k = idx >> 6;
        g_WoutT[d*Cc + k] = __float2bfloat16(out_W[k*Dd + d]);
    }
    for (int idx = gtid; idx < NBs*2*Cc; idx += NT){
        int s = idx >> 10, c = idx & 1023;
        float t = (float)s;
        int cc = (c < Cc) ? c : c - Cc;
        float coeff = 0.1f + (float)cc*(99.9f/511.0f);
        float e = coeff*t + phase[cc];
        g_temb[idx] = (c < Cc) ? sinf(e) : cosf(e);
    }
    if (gtid == 0){
        float cum = 0.f;
        g_betas[0] = 0.f;
        for (int j = 0; j < NBs; j++){
            float sg = 1.f/(1.f+expf(-grid_t[j]));
            cum += sg;
            g_betas[j+1] = cum;
        }
        float inv = 1.f/cum;
        for (int j = 1; j <= NBs; j++) g_betas[j] *= inv;
    }
    GB();

    // ── S1: t-MLP layer 1 (8-way K-split + shuffle reduce) ──
    {
        int oidx = gtid >> 3;
        int sl   = gtid & 7;
        int s = oidx >> 9, c = oidx & 511;
        float acc = 0.f;
        const float* tb = g_temb + s*2*Cc;
        int kb = sl*128;
        #pragma unroll 4
        for (int k = kb; k < kb+128; k++) acc += tb[k]*t_W1[k*Cc + c];
        #pragma unroll
        for (int o = 1; o < 8; o <<= 1) acc += __shfl_xor_sync(0xffffffffu, acc, o);
        if (sl == 0) g_tg1[oidx] = gelu_t(acc + t_b1[c]);
    }
    GB();

    // ── S2: t-MLP layer 2 + in_b → fused input bias ──
    {
        int oidx = gtid >> 3;
        int sl   = gtid & 7;
        int s = oidx >> 9, c = oidx & 511;
        float acc = 0.f;
        const float* gb = g_tg1 + s*Cc;
        int kb = sl*64;
        #pragma unroll 4
        for (int k = kb; k < kb+64; k++) acc += gb[k]*t_W2[k*Cc + c];
        #pragma unroll
        for (int o = 1; o < 8; o <<= 1) acc += __shfl_xor_sync(0xffffffffu, acc, o);
        if (sl == 0) g_bias1[oidx] = acc + t_b2[c] + in_b[c];
    }
    GB();

    int m0 = (blk >> 4) * 64;
    int n0 = (blk & 15) * 32;
    float* fold_out = g_osp + (size_t)(blk & 15)*Bp*Dd;

    for (int s = 0; s < NBs; s++){
        const float* x = out + (size_t)s*Bp*Dd;
        float* xn      = out + (size_t)(s+1)*Bp*Dd;
        int par = s & 1;

        // ── P1: input layer (K=64, fp32 x converted) + pairwise d2/hist ──
        gemm_bf16(x, Dd, 1, g_WinT, Dd, m0, n0, Dd, g_bias1 + s*Cc, 1, 0, nullptr, g_hA, Cc, sm);
        pairwise_tile(x, (blk>>3)*32, (blk&7)*64, g_hist[par], sm);
        GB();

        // ── P2-P4: hidden layers (P4 folds out-layer partials) ──
        gemm_bf16(g_hA, Cc, 0, g_WhT + 0*Cc*Cc, Cc, m0, n0, Cc, h_b + 0*Cc, 1, 0, nullptr, g_hB, Cc, sm);
        GB();
        gemm_bf16(g_hB, Cc, 0, g_WhT + 1*Cc*Cc, Cc, m0, n0, Cc, h_b + 1*Cc, 1, 0, nullptr, g_hA, Cc, sm);
        GB();
        gemm_bf16(g_hA, Cc, 0, g_WhT + 2*Cc*Cc, Cc, m0, n0, Cc, h_b + 2*Cc, 1, 1, fold_out, g_hB, Cc, sm);
        GB();

        // ── P6: median + tensorized repulsion + update ──
        {
            float ht = median_local(g_hist[par], sm);
            float inv_ht = 1.f/ht;
            int lane = tid & 31;
            int p = tid >> 6;
            int d = tid & 63;
            int i = blk*4 + p;

            for (int it = tid; it < 8192; it += TPB){
                int j = it >> 4, d4 = (it & 15)*4;
                float4 v = ldcg4(&x[j*Dd + d4]);
                sm->u.Xt[(d4+0)*SX + j] = __float2bfloat16(v.x);
                sm->u.Xt[(d4+1)*SX + j] = __float2bfloat16(v.y);
                sm->u.Xt[(d4+2)*SX + j] = __float2bfloat16(v.z);
                sm->u.Xt[(d4+3)*SX + j] = __float2bfloat16(v.w);
            }
            for (int it = tid; it < 12*SX/2; it += TPB)
                ((unsigned*)(sm->u.Aw + 4*SX))[it] = 0;
            if (tid < 4) sm->u.S[tid] = 0.f;
            __syncthreads();

            float sw = 0.f;
            #pragma unroll
            for (int q = 0; q < 8; q++){
                int j = d + q*64;
                float wv = expf(-ldcg1(&g_d2[i*Bp + j])*inv_ht);
                __nv_bfloat16 wb = __float2bfloat16(wv);
                sm->u.Aw[p*SX + j] = wb;
                sw += __bfloat162float(wb);
            }
            #pragma unroll
            for (int o = 16; o >= 1; o >>= 1) sw += __shfl_xor_sync(0xffffffffu, sw, o);
            if (lane == 0) atomicAdd(&sm->u.S[p], sw);

            if (d < MC){
                float sacc = 0.f;
                #pragma unroll 4
                for (int k = 0; k < Dd; k++){
                    float df = ldcg1(&x[i*Dd + k]) - means[d*Dd + k];
                    sacc += df*df;
                }
                float cm = -0.5f*sacc;
                float mx = cm;
                #pragma unroll
                for (int o = 4; o >= 1; o >>= 1) mx = fmaxf(mx, __shfl_xor_sync(0xffu, mx, o));
                float e = expf(cm - mx);
                float se = e;
                #pragma unroll
                for (int o = 4; o >= 1; o >>= 1) se += __shfl_xor_sync(0xffu, se, o);
                sm->u.wm[p][d] = e/se;
            }
            __syncthreads();

            {
                int w8 = tid >> 5;
                int g2 = lane >> 2, t2 = lane & 3;
                float accA[4] = {}, accB[4] = {};
                const __nv_bfloat16* Aw = sm->u.Aw;
                const __nv_bfloat16* Xt = sm->u.Xt + (size_t)(w8*8 + g2)*SX;
                #pragma unroll 8
                for (int kk = 0; kk < 32; kk++){
                    int kb = kk*16 + 2*t2;
                    unsigned a0 = *(const unsigned*)&Aw[g2*SX + kb];
                    unsigned a1 = *(const unsigned*)&Aw[(g2+8)*SX + kb];
                    unsigned a2 = *(const unsigned*)&Aw[g2*SX + kb + 8];
                    unsigned a3 = *(const unsigned*)&Aw[(g2+8)*SX + kb + 8];
                    unsigned b0 = *(const unsigned*)&Xt[kb];
                    unsigned b1 = *(const unsigned*)&Xt[kb + 8];
                    mma_bf16((kk & 1) ? accB : accA, a0, a1, a2, a3, b0, b1);
                }
                if (g2 < 4){
                    sm->u.T[g2*64 + w8*8 + 2*t2]     = accA[0] + accB[0];
                    sm->u.T[g2*64 + w8*8 + 2*t2 + 1] = accA[1] + accB[1];
                }
            }
            __syncthreads();

            float dt = eps[0];
            float t = g_betas[s];
            float s2dt = sqrtf(2.f*dt);
            float xi_d = ldcg1(&x[i*Dd + d]);
            float Sp = sm->u.S[p];
            float Tv = sm->u.T[p*64 + d];
            float r = xi_d*Sp - Tv;
            float wbar = 0.f;
            #pragma unroll
            for (int m = 0; m < MC; m++) wbar += sm->u.wm[p][m]*means[m*Dd + d];
            float sc = out_b[d];
            #pragma unroll
            for (int nt = 0; nt < 16; nt++)
                sc += ldcg1(&g_osp[((size_t)nt*Bp + i)*Dd + d]);
            float drift = t*wbar - xi_d - sc;
            float nv = noises[((size_t)s*Bp + i)*Dd + d];
            xn[i*Dd + d] = xi_d + dt*drift + s2dt*nv + 0.1f*dt*inv_ht*r;
            for (int idx = gtid; idx < NBINS; idx += NT) g_hist[par^1][idx] = 0;
        }
        GB();
    }
}

extern "C" void kernel_launch(void* const* d_in, const int* in_sizes, int n_in,
                              void* d_out, int out_size){
    const float* particles = (const float*)d_in[0];
    const float* noises    = (const float*)d_in[1];
    const float* grid_t    = (const float*)d_in[2];
    const float* eps       = (const float*)d_in[3];
    const float* means     = (const float*)d_in[4];
    const float* phase     = (const float*)d_in[5];
    const float* in_W      = (const float*)d_in[6];
    const float* in_b      = (const float*)d_in[7];
    const float* t_W1      = (const float*)d_in[8];
    const float* t_b1      = (const float*)d_in[9];
    const float* t_W2      = (const float*)d_in[10];
    const float* t_b2      = (const float*)d_in[11];
    const float* h_W       = (const float*)d_in[12];
    const float* h_b       = (const float*)d_in[13];
    const float* out_W     = (const float*)d_in[14];
    const float* out_b     = (const float*)d_in[15];
    float* out = (float*)d_out;

    static int smem_set = -1;
    int smem_bytes = (int)sizeof(Smem);
    if (smem_set < 0){
        cudaFuncSetAttribute(cmcd_fused, cudaFuncAttributeMaxDynamicSharedMemorySize, smem_bytes);
        smem_set = 1;
    }

    cmcd_fused<<<GRID, TPB, smem_bytes>>>(particles, noises, grid_t, eps, means, phase,
                                          in_W, in_b, t_W1, t_b1, t_W2, t_b2,
                                          h_W, h_b, out_W, out_b, out);
}